// round 2
// baseline (speedup 1.0000x reference)
#include <cuda_runtime.h>
#include <math.h>

#define NRANGE 13824
#define NDOM   1728
// feature column layout: [0,256) = repr, [256,384) = con, [384,512) = off

__device__ __align__(256) float g_range_feats[NRANGE * 512];
__device__ __align__(256) float g_domain_feats[NDOM * 512];
__device__ __align__(256) float g_pnum[2 * NRANGE * 64];
__device__ __align__(256) float g_pden[2 * NRANGE];
__device__ __align__(256) float g_poff[2 * NRANGE];

// ---------------------------------------------------------------------------
// Projection: out[m, 0:512] = (lat[m]+pos[m]) @ [Wr | Wc | Wo] + [br|bc|bo]
// BM=64, BN=64, BK=16, 128 threads, thread tile 8x4 (rows tr+8i, cols tc*4+j)
// ---------------------------------------------------------------------------
__global__ __launch_bounds__(128) void proj_kernel(
    const float* __restrict__ lat, const float* __restrict__ pos,
    const float* __restrict__ Wr, const float* __restrict__ br,
    const float* __restrict__ Wc, const float* __restrict__ bc,
    const float* __restrict__ Wo, const float* __restrict__ bo,
    float* __restrict__ outf)
{
    __shared__ float sA[64 * 20];   // [m][k], pad 20
    __shared__ float sB[16 * 68];   // [k][j], pad 68

    const int m0 = blockIdx.x * 64;
    const int j0 = blockIdx.y * 64;
    const float* W; const float* bias; int width; int jloc;
    if (j0 < 256)      { W = Wr; bias = br; width = 256; jloc = j0; }
    else if (j0 < 384) { W = Wc; bias = bc; width = 128; jloc = j0 - 256; }
    else               { W = Wo; bias = bo; width = 128; jloc = j0 - 384; }

    const int t  = threadIdx.x;
    const int tr = t >> 4;     // 0..7
    const int tc = t & 15;     // 0..15

    float acc[8][4];
#pragma unroll
    for (int i = 0; i < 8; i++)
#pragma unroll
        for (int j = 0; j < 4; j++) acc[i][j] = 0.f;

    for (int k0 = 0; k0 < 512; k0 += 16) {
#pragma unroll
        for (int q = 0; q < 2; q++) {
            int lin = q * 128 + t;
            int row = lin >> 2, k4 = lin & 3;
            size_t g = (size_t)(m0 + row) * 512 + k0 + k4 * 4;
            float4 a = *(const float4*)(lat + g);
            float4 p = *(const float4*)(pos + g);
            a.x += p.x; a.y += p.y; a.z += p.z; a.w += p.w;
            *(float4*)&sA[row * 20 + k4 * 4] = a;
        }
#pragma unroll
        for (int q = 0; q < 2; q++) {
            int lin = q * 128 + t;
            int kr = lin >> 4, j4 = lin & 15;
            *(float4*)&sB[kr * 68 + j4 * 4] =
                *(const float4*)(W + (size_t)(k0 + kr) * width + jloc + j4 * 4);
        }
        __syncthreads();
#pragma unroll
        for (int kk = 0; kk < 16; kk += 4) {
            float bf[4][4];
#pragma unroll
            for (int u = 0; u < 4; u++) {
                float4 B4 = *(float4*)&sB[(kk + u) * 68 + tc * 4];
                bf[u][0] = B4.x; bf[u][1] = B4.y; bf[u][2] = B4.z; bf[u][3] = B4.w;
            }
#pragma unroll
            for (int i = 0; i < 8; i++) {
                float4 A4 = *(float4*)&sA[(tr + 8 * i) * 20 + kk];
                float af[4] = {A4.x, A4.y, A4.z, A4.w};
#pragma unroll
                for (int j = 0; j < 4; j++)
                    acc[i][j] += af[0] * bf[0][j] + af[1] * bf[1][j]
                               + af[2] * bf[2][j] + af[3] * bf[3][j];
            }
        }
        __syncthreads();
    }

    float4 bv = *(const float4*)(bias + jloc + tc * 4);
#pragma unroll
    for (int i = 0; i < 8; i++) {
        float4 o;
        o.x = acc[i][0] + bv.x; o.y = acc[i][1] + bv.y;
        o.z = acc[i][2] + bv.z; o.w = acc[i][3] + bv.w;
        *(float4*)(outf + (size_t)(m0 + tr + 8 * i) * 512 + j0 + tc * 4) = o;
    }
}

// ---------------------------------------------------------------------------
// Fused attention. BM=32 range rows x one half of the 27 domain j-tiles
// (BN=64 each). A block 32x512 resident in smem. Single-pass softmax with
// fixed -20 shift. 128 threads. GEMM1 thread tile 4x4 (rows tr+8i, cols
// tc+16j). GEMM2 thread tile 4x4 (rows tr*4+i, cols tc*4+j).
// ---------------------------------------------------------------------------
__global__ __launch_bounds__(128, 2) void fused_kernel(const float* __restrict__ vflat)
{
    extern __shared__ float smem[];
    float* sA  = smem;                 // 32 x 516
    float* sBn = sA  + 32 * 516;       // 64 x 36  (domain feat chunk, [j][k])
    float* sPs = sBn + 64 * 36;        // 64 x 36  (P tile, [j][i] layout)
    float* sV  = sPs + 64 * 36;        // 64 x 68  (V tile, [j][c])
    __shared__ float denS[32], offS[32];

    const int t  = threadIdx.x;
    const int tr = t >> 4;             // 0..7
    const int tc = t & 15;             // 0..15
    const int mtile = blockIdx.x >> 1;
    const int hf    = blockIdx.x & 1;
    const int m0 = mtile * 32;
    const int jt_begin = hf ? 14 : 0;
    const int jt_end   = hf ? 27 : 14;

#pragma unroll 4
    for (int q = 0; q < 32; q++) {
        float4 a = *(const float4*)(g_range_feats + (size_t)(m0 + q) * 512 + t * 4);
        *(float4*)&sA[q * 516 + t * 4] = a;
    }
    if (t < 32) { denS[t] = 0.f; offS[t] = 0.f; }
    __syncthreads();

    float num[4][4];
#pragma unroll
    for (int i = 0; i < 4; i++)
#pragma unroll
        for (int j = 0; j < 4; j++) num[i][j] = 0.f;
    float den_acc[4] = {0.f, 0.f, 0.f, 0.f};
    float off_acc[4] = {0.f, 0.f, 0.f, 0.f};

    const float SCALE = 0.25f;                  // 1/(sqrt(256)*0.25)
    const float INVH  = 0.08838834764831845f;   // 1/sqrt(128)
    const float SHIFT = 20.0f;

    for (int jt = jt_begin; jt < jt_end; jt++) {
        const int j0 = jt * 64;

        // V tile (64 x 64)
#pragma unroll
        for (int q = 0; q < 8; q++) {
            int lin = q * 128 + t;
            int row = lin >> 4, c4 = lin & 15;
            *(float4*)&sV[row * 68 + c4 * 4] =
                *(const float4*)(vflat + (size_t)(j0 + row) * 64 + c4 * 4);
        }

        auto run_section = [&](int kbase, int nch, float (*acc)[4]) {
            for (int kc = 0; kc < nch; kc++) {
#pragma unroll
                for (int q = 0; q < 4; q++) {
                    int lin = q * 128 + t;
                    int j = lin >> 3, k4 = lin & 7;
                    *(float4*)&sBn[j * 36 + k4 * 4] =
                        *(const float4*)(g_domain_feats +
                            (size_t)(j0 + j) * 512 + kbase + kc * 32 + k4 * 4);
                }
                __syncthreads();
#pragma unroll
                for (int kk = 0; kk < 32; kk += 4) {
                    float af[4][4], bf[4][4];
#pragma unroll
                    for (int i = 0; i < 4; i++) {
                        float4 A4 = *(float4*)&sA[(tr + 8 * i) * 516 + kbase + kc * 32 + kk];
                        af[i][0] = A4.x; af[i][1] = A4.y; af[i][2] = A4.z; af[i][3] = A4.w;
                    }
#pragma unroll
                    for (int j = 0; j < 4; j++) {
                        float4 B4 = *(float4*)&sBn[(tc + 16 * j) * 36 + kk];
                        bf[j][0] = B4.x; bf[j][1] = B4.y; bf[j][2] = B4.z; bf[j][3] = B4.w;
                    }
#pragma unroll
                    for (int i = 0; i < 4; i++)
#pragma unroll
                        for (int j = 0; j < 4; j++)
                            acc[i][j] += af[i][0] * bf[j][0] + af[i][1] * bf[j][1]
                                       + af[i][2] * bf[j][2] + af[i][3] * bf[j][3];
                }
                __syncthreads();
            }
        };

        float acc[4][4], e[4][4];

        // ---- logits section (cols 0..255) ----
#pragma unroll
        for (int i = 0; i < 4; i++)
#pragma unroll
            for (int j = 0; j < 4; j++) acc[i][j] = 0.f;
        run_section(0, 8, acc);
#pragma unroll
        for (int i = 0; i < 4; i++)
#pragma unroll
            for (int j = 0; j < 4; j++) {
                e[i][j] = __expf(acc[i][j] * SCALE - SHIFT);
                den_acc[i] += e[i][j];
            }

        // ---- contrast section (cols 256..383) ----
#pragma unroll
        for (int i = 0; i < 4; i++)
#pragma unroll
            for (int j = 0; j < 4; j++) acc[i][j] = 0.f;
        run_section(256, 4, acc);
#pragma unroll
        for (int i = 0; i < 4; i++)
#pragma unroll
            for (int j = 0; j < 4; j++) {
                float con = tanhf(acc[i][j] * INVH) * 1.8f;
                sPs[(tc + 16 * j) * 36 + (tr + 8 * i)] = e[i][j] * con;
            }

        // ---- offset section (cols 384..511) ----
#pragma unroll
        for (int i = 0; i < 4; i++)
#pragma unroll
            for (int j = 0; j < 4; j++) acc[i][j] = 0.f;
        run_section(384, 4, acc);
#pragma unroll
        for (int i = 0; i < 4; i++)
#pragma unroll
            for (int j = 0; j < 4; j++)
                off_acc[i] += e[i][j] * tanhf(acc[i][j] * INVH);

        __syncthreads();  // sPs writes + sV visible

        // ---- GEMM2: num += P^T-layout tile x V tile ----
#pragma unroll 16
        for (int kj = 0; kj < 64; kj++) {
            float4 P4 = *(float4*)&sPs[kj * 36 + tr * 4];
            float4 V4 = *(float4*)&sV[kj * 68 + tc * 4];
            float pf[4] = {P4.x, P4.y, P4.z, P4.w};
            float vf[4] = {V4.x, V4.y, V4.z, V4.w};
#pragma unroll
            for (int i = 0; i < 4; i++)
#pragma unroll
                for (int j = 0; j < 4; j++)
                    num[i][j] += pf[i] * vf[j];
        }
        __syncthreads();  // before next tile overwrites sPs/sV/sBn
    }

#pragma unroll
    for (int i = 0; i < 4; i++) {
        atomicAdd(&denS[tr + 8 * i], den_acc[i]);
        atomicAdd(&offS[tr + 8 * i], off_acc[i]);
    }
    __syncthreads();

    if (t < 32) {
        g_pden[(size_t)hf * NRANGE + m0 + t] = denS[t];
        g_poff[(size_t)hf * NRANGE + m0 + t] = offS[t];
    }
    const size_t nbase = (size_t)hf * NRANGE * 64;
#pragma unroll
    for (int i = 0; i < 4; i++) {
        float4 o;
        o.x = num[i][0]; o.y = num[i][1]; o.z = num[i][2]; o.w = num[i][3];
        *(float4*)(g_pnum + nbase + (size_t)(m0 + tr * 4 + i) * 64 + tc * 4) = o;
    }
}

// ---------------------------------------------------------------------------
__global__ __launch_bounds__(256) void epilogue_kernel(float* __restrict__ out)
{
    int idx = blockIdx.x * 256 + threadIdx.x;
    if (idx >= NRANGE * 64) return;
    int row = idx >> 6;
    float d = g_pden[row] + g_pden[NRANGE + row];
    float o = g_poff[row] + g_poff[NRANGE + row];
    out[idx] = (g_pnum[idx] + g_pnum[NRANGE * 64 + idx] + o) / d;
}

// ---------------------------------------------------------------------------
extern "C" void kernel_launch(void* const* d_in, const int* in_sizes, int n_in,
                              void* d_out, int out_size)
{
    (void)in_sizes; (void)n_in; (void)out_size;
    const float* pooled = (const float*)d_in[0];
    const float* rlat   = (const float*)d_in[1];
    const float* dlat   = (const float*)d_in[2];
    const float* rpos   = (const float*)d_in[3];
    const float* dpos   = (const float*)d_in[4];
    const float* Wrp = (const float*)d_in[5];   const float* brp = (const float*)d_in[6];
    const float* Wdp = (const float*)d_in[7];   const float* bdp = (const float*)d_in[8];
    const float* Wrc = (const float*)d_in[9];   const float* brc = (const float*)d_in[10];
    const float* Wdc = (const float*)d_in[11];  const float* bdc = (const float*)d_in[12];
    const float* Wro = (const float*)d_in[13];  const float* bro = (const float*)d_in[14];
    const float* Wdo = (const float*)d_in[15];  const float* bdo = (const float*)d_in[16];
    float* out = (float*)d_out;

    float* rfeat; float* dfeat;
    cudaGetSymbolAddress((void**)&rfeat, g_range_feats);
    cudaGetSymbolAddress((void**)&dfeat, g_domain_feats);

    static bool configured = false;
    if (!configured) {
        cudaFuncSetAttribute(fused_kernel,
                             cudaFuncAttributeMaxDynamicSharedMemorySize,
                             (32 * 516 + 64 * 36 + 64 * 36 + 64 * 68) * 4);
        configured = true;
    }

    proj_kernel<<<dim3(NRANGE / 64, 8), 128>>>(rlat, rpos, Wrp, brp, Wrc, brc,
                                               Wro, bro, rfeat);
    proj_kernel<<<dim3(NDOM / 64, 8), 128>>>(dlat, dpos, Wdp, bdp, Wdc, bdc,
                                             Wdo, bdo, dfeat);

    size_t smem = (size_t)(32 * 516 + 64 * 36 + 64 * 36 + 64 * 68) * 4;
    fused_kernel<<<(NRANGE / 32) * 2, 128, smem>>>(pooled);

    epilogue_kernel<<<(NRANGE * 64 + 255) / 256, 256>>>(out);
}

// round 4
// speedup vs baseline: 2.2717x; 2.2717x over previous
#include <cuda_runtime.h>
#include <cuda_bf16.h>
#include <math.h>
#include <stdint.h>

#define NR 13824
#define ND 1728

// ---------------------------------------------------------------------------
// PTX helpers (sm_80-era instructions only: valid under compute_100)
// ---------------------------------------------------------------------------
__device__ __forceinline__ uint32_t smem_u32(const void* p) {
    uint32_t a;
    asm("{ .reg .u64 t; cvta.to.shared.u64 t, %1; cvt.u32.u64 %0, t; }"
        : "=r"(a) : "l"(p));
    return a;
}
__device__ __forceinline__ void cp16(uint32_t dst, const void* src) {
    asm volatile("cp.async.cg.shared.global [%0], [%1], 16;"
                 :: "r"(dst), "l"(src) : "memory");
}
#define CP_COMMIT() asm volatile("cp.async.commit_group;" ::: "memory")
#define CP_WAIT0()  asm volatile("cp.async.wait_group 0;" ::: "memory")

__device__ __forceinline__ void ldsm4(uint32_t& r0, uint32_t& r1,
                                      uint32_t& r2, uint32_t& r3, uint32_t a) {
    asm volatile("ldmatrix.sync.aligned.m8n8.x4.shared.b16 {%0,%1,%2,%3}, [%4];"
                 : "=r"(r0), "=r"(r1), "=r"(r2), "=r"(r3) : "r"(a));
}
__device__ __forceinline__ void mma16816(float* c, uint32_t a0, uint32_t a1,
                                         uint32_t a2, uint32_t a3,
                                         uint32_t b0, uint32_t b1) {
    asm volatile(
        "mma.sync.aligned.m16n8k16.row.col.f32.bf16.bf16.f32 "
        "{%0,%1,%2,%3}, {%4,%5,%6,%7}, {%8,%9}, {%0,%1,%2,%3};"
        : "+f"(c[0]), "+f"(c[1]), "+f"(c[2]), "+f"(c[3])
        : "r"(a0), "r"(a1), "r"(a2), "r"(a3), "r"(b0), "r"(b1));
}
__device__ __forceinline__ uint32_t packbf(float lo, float hi) {
    uint32_t r;
    asm("cvt.rn.bf16x2.f32 %0, %1, %2;" : "=r"(r) : "f"(hi), "f"(lo));
    return r;
}
__device__ __forceinline__ float bf_lo(uint32_t u) { return __uint_as_float(u << 16); }
__device__ __forceinline__ float bf_hi(uint32_t u) { return __uint_as_float(u & 0xFFFF0000u); }

__device__ __forceinline__ float tanh_fast(float x) {
    float ax = fabsf(x);
    float s = __expf(-2.f * ax);
    float r = __fdividef(1.f - s, 1.f + s);
    return copysignf(r, x);
}

// ---------------------------------------------------------------------------
// Scratch
// ---------------------------------------------------------------------------
__device__ __align__(256) __nv_bfloat16 g_rhi[NR * 512];
__device__ __align__(256) __nv_bfloat16 g_rlo[NR * 512];
__device__ __align__(256) __nv_bfloat16 g_dhi[ND * 512];
__device__ __align__(256) __nv_bfloat16 g_dlo[ND * 512];
__device__ __align__(256) float g_pnum[4 * NR * 64];
__device__ __align__(256) float g_pden[4 * NR];
__device__ __align__(256) float g_poff[4 * NR];

// ---------------------------------------------------------------------------
// Projection (fp32 FFMA): out[m,0:512] = (lat+pos) @ [Wr|Wc|Wo] + b, emitted
// as split bf16 (hi, lo). Column layout: [0,256) repr, [256,384) con,
// [384,512) off.
// ---------------------------------------------------------------------------
__global__ __launch_bounds__(128) void proj_kernel(
    const float* __restrict__ lat, const float* __restrict__ pos,
    const float* __restrict__ Wr, const float* __restrict__ br,
    const float* __restrict__ Wc, const float* __restrict__ bc,
    const float* __restrict__ Wo, const float* __restrict__ bo,
    __nv_bfloat16* __restrict__ ohi, __nv_bfloat16* __restrict__ olo)
{
    __shared__ float sA[64 * 20];
    __shared__ float sB[16 * 68];

    const int m0 = blockIdx.x * 64;
    const int j0 = blockIdx.y * 64;
    const float* W; const float* bias; int width; int jloc;
    if (j0 < 256)      { W = Wr; bias = br; width = 256; jloc = j0; }
    else if (j0 < 384) { W = Wc; bias = bc; width = 128; jloc = j0 - 256; }
    else               { W = Wo; bias = bo; width = 128; jloc = j0 - 384; }

    const int t  = threadIdx.x;
    const int tr = t >> 4;
    const int tc = t & 15;

    float acc[8][4];
#pragma unroll
    for (int i = 0; i < 8; i++)
#pragma unroll
        for (int j = 0; j < 4; j++) acc[i][j] = 0.f;

    for (int k0 = 0; k0 < 512; k0 += 16) {
#pragma unroll
        for (int q = 0; q < 2; q++) {
            int lin = q * 128 + t;
            int row = lin >> 2, k4 = lin & 3;
            size_t g = (size_t)(m0 + row) * 512 + k0 + k4 * 4;
            float4 a = *(const float4*)(lat + g);
            float4 p = *(const float4*)(pos + g);
            a.x += p.x; a.y += p.y; a.z += p.z; a.w += p.w;
            *(float4*)&sA[row * 20 + k4 * 4] = a;
        }
#pragma unroll
        for (int q = 0; q < 2; q++) {
            int lin = q * 128 + t;
            int kr = lin >> 4, j4 = lin & 15;
            *(float4*)&sB[kr * 68 + j4 * 4] =
                *(const float4*)(W + (size_t)(k0 + kr) * width + jloc + j4 * 4);
        }
        __syncthreads();
#pragma unroll
        for (int kk = 0; kk < 16; kk += 4) {
            float bf[4][4];
#pragma unroll
            for (int u = 0; u < 4; u++) {
                float4 B4 = *(float4*)&sB[(kk + u) * 68 + tc * 4];
                bf[u][0] = B4.x; bf[u][1] = B4.y; bf[u][2] = B4.z; bf[u][3] = B4.w;
            }
#pragma unroll
            for (int i = 0; i < 8; i++) {
                float4 A4 = *(float4*)&sA[(tr + 8 * i) * 20 + kk];
                float af[4] = {A4.x, A4.y, A4.z, A4.w};
#pragma unroll
                for (int j = 0; j < 4; j++)
                    acc[i][j] += af[0] * bf[0][j] + af[1] * bf[1][j]
                               + af[2] * bf[2][j] + af[3] * bf[3][j];
            }
        }
        __syncthreads();
    }

    float4 bv = *(const float4*)(bias + jloc + tc * 4);
#pragma unroll
    for (int i = 0; i < 8; i++) {
        float v[4] = {acc[i][0] + bv.x, acc[i][1] + bv.y,
                      acc[i][2] + bv.z, acc[i][3] + bv.w};
        __nv_bfloat16 h[4], l[4];
#pragma unroll
        for (int j = 0; j < 4; j++) {
            h[j] = __float2bfloat16_rn(v[j]);
            l[j] = __float2bfloat16_rn(v[j] - __bfloat162float(h[j]));
        }
        size_t o = (size_t)(m0 + tr + 8 * i) * 512 + j0 + tc * 4;
        *(uint2*)(ohi + o) = *(uint2*)h;
        *(uint2*)(olo + o) = *(uint2*)l;
    }
}

// ---------------------------------------------------------------------------
// Fused attention via mma.sync bf16 (split hi/lo, 3-term).
// CTA = 128 range rows x one quarter of 27 domain tiles (N=64 each).
// 8 warps, warp = 16 rows x 64 cols. K chunks of 64, cp.async double buffer.
// ---------------------------------------------------------------------------
#define SA_LO 16384u
#define SB0   65536u
#define SB_LO 8192u
#define SVH   98304u
#define SVL   106496u
#define SMEMSZ 114688

__global__ __launch_bounds__(256, 1)
void fused_kernel(const float* __restrict__ vflat)
{
    extern __shared__ char dsm[];
    const uint32_t sbase = smem_u32(dsm);

    const int t    = threadIdx.x;
    const int w    = t >> 5;
    const int lane = t & 31;
    const int m0   = blockIdx.x * 128;
    const int q    = blockIdx.y;
    const int qs0[5] = {0, 7, 14, 21, 27};
    const int jt0 = qs0[q], jt1 = qs0[q + 1];

    // per-thread ldmatrix addressing constants
    const uint32_t kOff = (lane >> 4) * 16;          // k-seg byte within 32B step
    const uint32_t xm   = (lane & 7) << 4;           // swizzle xor mask
    const uint32_t aRow = sbase + (uint32_t)(w * 16 + (lane & 15)) * 128;
    const uint32_t bRow = sbase + SB0 + (uint32_t)(lane & 15) * 128;
    const uint32_t vRow = sbase + SVH + (uint32_t)(lane & 15) * 128;

    float num[8][4];
#pragma unroll
    for (int j = 0; j < 8; j++)
#pragma unroll
        for (int v = 0; v < 4; v++) num[j][v] = 0.f;
    float den0 = 0.f, den1 = 0.f, off0 = 0.f, off1 = 0.f;

    const float SCALE = 0.25f;
    const float INVH  = 0.08838834764831845f;
    const float SHIFT = 20.0f;

    for (int jt = jt0; jt < jt1; jt++) {
        const int j0 = jt * 64;
        __syncthreads();   // guard sVt + buffers against previous tile readers

        // ---- build V^T tile (hi/lo bf16), rows = out-col c, cols = domain ----
#pragma unroll
        for (int qq = 0; qq < 4; qq++) {
            int idx = qq * 256 + t;                 // 1024 float4 reads
            int dom = idx >> 4, c4 = (idx & 15) * 4;
            float4 vv = *(const float4*)(vflat + (size_t)(j0 + dom) * 64 + c4);
            float va[4] = {vv.x, vv.y, vv.z, vv.w};
#pragma unroll
            for (int k = 0; k < 4; k++) {
                int c = c4 + k;
                uint32_t d = (uint32_t)(c * 128 + dom * 2) ^ ((uint32_t)(c & 7) << 4);
                __nv_bfloat16 h = __float2bfloat16_rn(va[k]);
                __nv_bfloat16 l = __float2bfloat16_rn(va[k] - __bfloat162float(h));
                *(__nv_bfloat16*)(dsm + SVH + d) = h;
                *(__nv_bfloat16*)(dsm + SVL + d) = l;
            }
        }

        // ---- prefetch chunk 0 ----
        {
            const int kb = 0;
            uint32_t aB = sbase;                    // buf 0
#pragma unroll
            for (int qq = 0; qq < 4; qq++) {
                int idx = qq * 256 + t;
                int row = idx >> 3, seg = idx & 7;
                uint32_t d = aB + (((uint32_t)(row * 128 + seg * 16)) ^ ((uint32_t)(row & 7) << 4));
                size_t g = (size_t)(m0 + row) * 512 + kb + seg * 8;
                cp16(d, g_rhi + g);
                cp16(d + SA_LO, g_rlo + g);
            }
            uint32_t bB = sbase + SB0;
#pragma unroll
            for (int qq = 0; qq < 2; qq++) {
                int idx = qq * 256 + t;
                int row = idx >> 3, seg = idx & 7;
                uint32_t d = bB + (((uint32_t)(row * 128 + seg * 16)) ^ ((uint32_t)(row & 7) << 4));
                size_t g = (size_t)(j0 + row) * 512 + kb + seg * 8;
                cp16(d, g_dhi + g);
                cp16(d + SB_LO, g_dlo + g);
            }
            CP_COMMIT();
        }

        float acc[8][4];
#pragma unroll
        for (int j = 0; j < 8; j++)
#pragma unroll
            for (int v = 0; v < 4; v++) acc[j][v] = 0.f;
        float e[8][4];
        uint32_t paH[4][4], paL[4][4];

#pragma unroll 1
        for (int s = 0; s < 8; s++) {
            CP_WAIT0();
            __syncthreads();

            // prefetch next chunk into the other buffer
            if (s < 7) {
                int sn = s + 1;
                int kb = (sn < 4) ? sn * 64 : ((sn < 6) ? 384 + (sn - 4) * 64
                                                        : 256 + (sn - 6) * 64);
                uint32_t aB = sbase + (uint32_t)((sn & 1) * 32768);
#pragma unroll
                for (int qq = 0; qq < 4; qq++) {
                    int idx = qq * 256 + t;
                    int row = idx >> 3, seg = idx & 7;
                    uint32_t d = aB + (((uint32_t)(row * 128 + seg * 16)) ^ ((uint32_t)(row & 7) << 4));
                    size_t g = (size_t)(m0 + row) * 512 + kb + seg * 8;
                    cp16(d, g_rhi + g);
                    cp16(d + SA_LO, g_rlo + g);
                }
                uint32_t bB = sbase + SB0 + (uint32_t)((sn & 1) * 16384);
#pragma unroll
                for (int qq = 0; qq < 2; qq++) {
                    int idx = qq * 256 + t;
                    int row = idx >> 3, seg = idx & 7;
                    uint32_t d = bB + (((uint32_t)(row * 128 + seg * 16)) ^ ((uint32_t)(row & 7) << 4));
                    size_t g = (size_t)(j0 + row) * 512 + kb + seg * 8;
                    cp16(d, g_dhi + g);
                    cp16(d + SB_LO, g_dlo + g);
                }
            }
            CP_COMMIT();

            // ---- compute this chunk ----
            const uint32_t aHi = aRow + (uint32_t)((s & 1) * 32768);
            const uint32_t bHi = bRow + (uint32_t)((s & 1) * 16384);
#pragma unroll
            for (int ks = 0; ks < 4; ks++) {
                uint32_t ko = ((uint32_t)(ks * 32) + kOff) ^ xm;
                uint32_t ah0, ah1, ah2, ah3, al0, al1, al2, al3;
                ldsm4(ah0, ah1, ah2, ah3, aHi + ko);
                ldsm4(al0, al1, al2, al3, aHi + SA_LO + ko);
#pragma unroll
                for (int p = 0; p < 4; p++) {
                    uint32_t bh0, bh1, bh2, bh3, bl0, bl1, bl2, bl3;
                    uint32_t ba = bHi + (uint32_t)(p * 2048) + ko;
                    ldsm4(bh0, bh1, bh2, bh3, ba);
                    ldsm4(bl0, bl1, bl2, bl3, ba + SB_LO);
                    mma16816(acc[2 * p],     ah0, ah1, ah2, ah3, bh0, bh2);
                    mma16816(acc[2 * p],     ah0, ah1, ah2, ah3, bl0, bl2);
                    mma16816(acc[2 * p],     al0, al1, al2, al3, bh0, bh2);
                    mma16816(acc[2 * p + 1], ah0, ah1, ah2, ah3, bh1, bh3);
                    mma16816(acc[2 * p + 1], ah0, ah1, ah2, ah3, bl1, bl3);
                    mma16816(acc[2 * p + 1], al0, al1, al2, al3, bh1, bh3);
                }
            }

            // ---- section boundaries ----
            if (s == 3) {          // logits done -> e, den
#pragma unroll
                for (int j = 0; j < 8; j++) {
#pragma unroll
                    for (int v = 0; v < 4; v++) {
                        e[j][v] = __expf(acc[j][v] * SCALE - SHIFT);
                        acc[j][v] = 0.f;
                    }
                    den0 += e[j][0] + e[j][1];
                    den1 += e[j][2] + e[j][3];
                }
            } else if (s == 5) {   // offset done
#pragma unroll
                for (int j = 0; j < 8; j++) {
                    off0 += e[j][0] * tanh_fast(acc[j][0] * INVH)
                          + e[j][1] * tanh_fast(acc[j][1] * INVH);
                    off1 += e[j][2] * tanh_fast(acc[j][2] * INVH)
                          + e[j][3] * tanh_fast(acc[j][3] * INVH);
#pragma unroll
                    for (int v = 0; v < 4; v++) acc[j][v] = 0.f;
                }
            } else if (s == 7) {   // contrast done -> P fragments (hi/lo)
#pragma unroll
                for (int j = 0; j < 8; j++) {
                    float p0 = e[j][0] * 1.8f * tanh_fast(acc[j][0] * INVH);
                    float p1 = e[j][1] * 1.8f * tanh_fast(acc[j][1] * INVH);
                    float p2 = e[j][2] * 1.8f * tanh_fast(acc[j][2] * INVH);
                    float p3 = e[j][3] * 1.8f * tanh_fast(acc[j][3] * INVH);
                    uint32_t h01 = packbf(p0, p1), h23 = packbf(p2, p3);
                    uint32_t l01 = packbf(p0 - bf_lo(h01), p1 - bf_hi(h01));
                    uint32_t l23 = packbf(p2 - bf_lo(h23), p3 - bf_hi(h23));
                    int kt = j >> 1, ix = (j & 1) * 2;
                    paH[kt][ix] = h01; paH[kt][ix + 1] = h23;
                    paL[kt][ix] = l01; paL[kt][ix + 1] = l23;
                }
            }
        }

        // ---- GEMM2: num += P @ V  (V^T fragments from smem) ----
#pragma unroll
        for (int kt = 0; kt < 4; kt++) {
            uint32_t ko = ((uint32_t)(kt * 32) + kOff) ^ xm;
#pragma unroll
            for (int p = 0; p < 4; p++) {
                uint32_t vh0, vh1, vh2, vh3, vl0, vl1, vl2, vl3;
                uint32_t va = vRow + (uint32_t)(p * 2048) + ko;
                ldsm4(vh0, vh1, vh2, vh3, va);
                ldsm4(vl0, vl1, vl2, vl3, va + (SVL - SVH));
                mma16816(num[2 * p],     paH[kt][0], paH[kt][1], paH[kt][2], paH[kt][3], vh0, vh2);
                mma16816(num[2 * p],     paH[kt][0], paH[kt][1], paH[kt][2], paH[kt][3], vl0, vl2);
                mma16816(num[2 * p],     paL[kt][0], paL[kt][1], paL[kt][2], paL[kt][3], vh0, vh2);
                mma16816(num[2 * p + 1], paH[kt][0], paH[kt][1], paH[kt][2], paH[kt][3], vh1, vh3);
                mma16816(num[2 * p + 1], paH[kt][0], paH[kt][1], paH[kt][2], paH[kt][3], vl1, vl3);
                mma16816(num[2 * p + 1], paL[kt][0], paL[kt][1], paL[kt][2], paL[kt][3], vh1, vh3);
            }
        }
    }

    // ---- write partials ----
    const int row0 = m0 + w * 16 + (lane >> 2);
    const int row1 = row0 + 8;
    const int colb = (lane & 3) * 2;
    float* np = g_pnum + (size_t)q * NR * 64;
#pragma unroll
    for (int j = 0; j < 8; j++) {
        *(float2*)(np + (size_t)row0 * 64 + j * 8 + colb) = make_float2(num[j][0], num[j][1]);
        *(float2*)(np + (size_t)row1 * 64 + j * 8 + colb) = make_float2(num[j][2], num[j][3]);
    }
#pragma unroll
    for (int m = 1; m < 4; m <<= 1) {
        den0 += __shfl_xor_sync(0xFFFFFFFFu, den0, m);
        den1 += __shfl_xor_sync(0xFFFFFFFFu, den1, m);
        off0 += __shfl_xor_sync(0xFFFFFFFFu, off0, m);
        off1 += __shfl_xor_sync(0xFFFFFFFFu, off1, m);
    }
    if ((lane & 3) == 0) {
        g_pden[(size_t)q * NR + row0] = den0;
        g_pden[(size_t)q * NR + row1] = den1;
        g_poff[(size_t)q * NR + row0] = off0;
        g_poff[(size_t)q * NR + row1] = off1;
    }
}

// ---------------------------------------------------------------------------
__global__ __launch_bounds__(256) void epilogue_kernel(float* __restrict__ out)
{
    int idx = blockIdx.x * 256 + threadIdx.x;
    if (idx >= NR * 64) return;
    int row = idx >> 6;
    float num = 0.f, den = 0.f, off = 0.f;
#pragma unroll
    for (int q = 0; q < 4; q++) {
        num += g_pnum[(size_t)q * NR * 64 + idx];
        den += g_pden[(size_t)q * NR + row];
        off += g_poff[(size_t)q * NR + row];
    }
    out[idx] = (num + off) / den;
}

// ---------------------------------------------------------------------------
extern "C" void kernel_launch(void* const* d_in, const int* in_sizes, int n_in,
                              void* d_out, int out_size)
{
    (void)in_sizes; (void)n_in; (void)out_size;
    const float* pooled = (const float*)d_in[0];
    const float* rlat   = (const float*)d_in[1];
    const float* dlat   = (const float*)d_in[2];
    const float* rpos   = (const float*)d_in[3];
    const float* dpos   = (const float*)d_in[4];
    const float* Wrp = (const float*)d_in[5];   const float* brp = (const float*)d_in[6];
    const float* Wdp = (const float*)d_in[7];   const float* bdp = (const float*)d_in[8];
    const float* Wrc = (const float*)d_in[9];   const float* brc = (const float*)d_in[10];
    const float* Wdc = (const float*)d_in[11];  const float* bdc = (const float*)d_in[12];
    const float* Wro = (const float*)d_in[13];  const float* bro = (const float*)d_in[14];
    const float* Wdo = (const float*)d_in[15];  const float* bdo = (const float*)d_in[16];
    float* out = (float*)d_out;

    __nv_bfloat16 *rhi, *rlo, *dhi, *dlo;
    cudaGetSymbolAddress((void**)&rhi, g_rhi);
    cudaGetSymbolAddress((void**)&rlo, g_rlo);
    cudaGetSymbolAddress((void**)&dhi, g_dhi);
    cudaGetSymbolAddress((void**)&dlo, g_dlo);

    cudaFuncSetAttribute(fused_kernel,
                         cudaFuncAttributeMaxDynamicSharedMemorySize, SMEMSZ);

    proj_kernel<<<dim3(NR / 64, 8), 128>>>(rlat, rpos, Wrp, brp, Wrc, brc,
                                           Wro, bro, rhi, rlo);
    proj_kernel<<<dim3(ND / 64, 8), 128>>>(dlat, dpos, Wdp, bdp, Wdc, bdc,
                                           Wdo, bdo, dhi, dlo);

    fused_kernel<<<dim3(108, 4), 256, SMEMSZ>>>(pooled);

    epilogue_kernel<<<(NR * 64 + 255) / 256, 256>>>(out);
}

// round 5
// speedup vs baseline: 3.0802x; 1.3559x over previous
#include <cuda_runtime.h>
#include <cuda_bf16.h>
#include <math.h>
#include <stdint.h>

#define NR 13824
#define ND 1728
#define NTOT (NR + ND)   // 15552

// ---------------------------------------------------------------------------
// PTX helpers (sm_80-era instructions only: valid under compute_100)
// ---------------------------------------------------------------------------
__device__ __forceinline__ uint32_t smem_u32(const void* p) {
    uint32_t a;
    asm("{ .reg .u64 t; cvta.to.shared.u64 t, %1; cvt.u32.u64 %0, t; }"
        : "=r"(a) : "l"(p));
    return a;
}
__device__ __forceinline__ void cp16(uint32_t dst, const void* src) {
    asm volatile("cp.async.cg.shared.global [%0], [%1], 16;"
                 :: "r"(dst), "l"(src) : "memory");
}
#define CP_COMMIT() asm volatile("cp.async.commit_group;" ::: "memory")
#define CP_WAIT0()  asm volatile("cp.async.wait_group 0;" ::: "memory")

__device__ __forceinline__ void ldsm4(uint32_t& r0, uint32_t& r1,
                                      uint32_t& r2, uint32_t& r3, uint32_t a) {
    asm volatile("ldmatrix.sync.aligned.m8n8.x4.shared.b16 {%0,%1,%2,%3}, [%4];"
                 : "=r"(r0), "=r"(r1), "=r"(r2), "=r"(r3) : "r"(a));
}
__device__ __forceinline__ void mma16816(float* c, uint32_t a0, uint32_t a1,
                                         uint32_t a2, uint32_t a3,
                                         uint32_t b0, uint32_t b1) {
    asm volatile(
        "mma.sync.aligned.m16n8k16.row.col.f32.bf16.bf16.f32 "
        "{%0,%1,%2,%3}, {%4,%5,%6,%7}, {%8,%9}, {%0,%1,%2,%3};"
        : "+f"(c[0]), "+f"(c[1]), "+f"(c[2]), "+f"(c[3])
        : "r"(a0), "r"(a1), "r"(a2), "r"(a3), "r"(b0), "r"(b1));
}
__device__ __forceinline__ uint32_t packbf(float lo, float hi) {
    uint32_t r;
    asm("cvt.rn.bf16x2.f32 %0, %1, %2;" : "=r"(r) : "f"(hi), "f"(lo));
    return r;
}
__device__ __forceinline__ float bf_lo(uint32_t u) { return __uint_as_float(u << 16); }
__device__ __forceinline__ float bf_hi(uint32_t u) { return __uint_as_float(u & 0xFFFF0000u); }

__device__ __forceinline__ float tanh_fast(float x) {
    float ax = fabsf(x);
    float s = __expf(-2.f * ax);
    float r = __fdividef(1.f - s, 1.f + s);
    return copysignf(r, x);
}

// ---------------------------------------------------------------------------
// Scratch
// ---------------------------------------------------------------------------
__device__ __align__(256) __nv_bfloat16 g_rhi[NR * 512];
__device__ __align__(256) __nv_bfloat16 g_rlo[NR * 512];
__device__ __align__(256) __nv_bfloat16 g_dhi[ND * 512];
__device__ __align__(256) __nv_bfloat16 g_dlo[ND * 512];
__device__ __align__(256) __nv_bfloat16 g_inh[NTOT * 512];   // (lat+pos) hi
__device__ __align__(256) __nv_bfloat16 g_inl[NTOT * 512];   // (lat+pos) lo
__device__ __align__(256) __nv_bfloat16 g_wth[2 * 512 * 512]; // W^T hi [side][n][k]
__device__ __align__(256) __nv_bfloat16 g_wtl[2 * 512 * 512]; // W^T lo
__device__ __align__(256) float g_pnum[4 * NR * 64];
__device__ __align__(256) float g_pden[4 * NR];
__device__ __align__(256) float g_poff[4 * NR];

// ---------------------------------------------------------------------------
// prep_in: g_in{h,l}[row0+r][k] = split(lat[r][k] + pos[r][k])
// ---------------------------------------------------------------------------
__global__ __launch_bounds__(256) void prep_in(
    const float* __restrict__ lat, const float* __restrict__ pos,
    int nrows, int row0)
{
    size_t idx = (size_t)blockIdx.x * 256 + threadIdx.x;   // group of 4 elems
    size_t total = (size_t)nrows * 128;
    if (idx >= total) return;
    size_t r = idx >> 7;
    int c4 = (int)(idx & 127) * 4;
    size_t g = r * 512 + c4;
    float4 a = *(const float4*)(lat + g);
    float4 p = *(const float4*)(pos + g);
    float v[4] = {a.x + p.x, a.y + p.y, a.z + p.z, a.w + p.w};
    __nv_bfloat16 h[4], l[4];
#pragma unroll
    for (int j = 0; j < 4; j++) {
        h[j] = __float2bfloat16_rn(v[j]);
        l[j] = __float2bfloat16_rn(v[j] - __bfloat162float(h[j]));
    }
    size_t o = (size_t)(row0 + r) * 512 + c4;
    *(uint2*)(g_inh + o) = *(uint2*)h;
    *(uint2*)(g_inl + o) = *(uint2*)l;
}

// ---------------------------------------------------------------------------
// prep_w: g_wt{h,l}[side][n][k] = split(W[k][n]) for combined [Wp|Wc|Wo]
// grid (512, 2), 128 threads; thread handles 4 consecutive k.
// ---------------------------------------------------------------------------
__global__ __launch_bounds__(128) void prep_w(
    const float* __restrict__ Wrp, const float* __restrict__ Wrc,
    const float* __restrict__ Wro, const float* __restrict__ Wdp,
    const float* __restrict__ Wdc, const float* __restrict__ Wdo)
{
    const int n    = blockIdx.x;
    const int side = blockIdx.y;
    const int k0   = threadIdx.x * 4;

    const float* W; int width; int nloc;
    if (n < 256)      { W = side ? Wdp : Wrp; width = 256; nloc = n; }
    else if (n < 384) { W = side ? Wdc : Wrc; width = 128; nloc = n - 256; }
    else              { W = side ? Wdo : Wro; width = 128; nloc = n - 384; }

    __nv_bfloat16 h[4], l[4];
#pragma unroll
    for (int j = 0; j < 4; j++) {
        float v = W[(size_t)(k0 + j) * width + nloc];
        h[j] = __float2bfloat16_rn(v);
        l[j] = __float2bfloat16_rn(v - __bfloat162float(h[j]));
    }
    size_t o = (size_t)side * 512 * 512 + (size_t)n * 512 + k0;
    *(uint2*)(g_wth + o) = *(uint2*)h;
    *(uint2*)(g_wtl + o) = *(uint2*)l;
}

// ---------------------------------------------------------------------------
// proj_mma: features[m, 0:512] = in[m] @ W^T[side] + bias, emitted split.
// CTA = 128 rows x 64 cols; K=512 in 8 cp.async double-buffered chunks;
// 3-term bf16 split mma. Rows clamped/predicated for the domain tail.
// smem: A hi/lo 2 bufs (2*32768) @0, B hi/lo 2 bufs (2*16384) @65536 -> 96KB.
// ---------------------------------------------------------------------------
#define PJ_ALO 16384u
#define PJ_B0  65536u
#define PJ_BLO 8192u
#define PJ_SMEM 98304

__global__ __launch_bounds__(256, 1) void proj_mma(
    int row0_in, int Mrows, int side,
    const float* __restrict__ bp, const float* __restrict__ bc,
    const float* __restrict__ bo,
    __nv_bfloat16* __restrict__ ohi, __nv_bfloat16* __restrict__ olo)
{
    extern __shared__ char dsm[];
    const uint32_t sbase = smem_u32(dsm);

    const int t    = threadIdx.x;
    const int w    = t >> 5;
    const int lane = t & 31;
    const int m0   = blockIdx.x * 128;
    const int j0   = blockIdx.y * 64;

    const float* bias; int jloc;
    if (j0 < 256)      { bias = bp; jloc = j0; }
    else if (j0 < 384) { bias = bc; jloc = j0 - 256; }
    else               { bias = bo; jloc = j0 - 384; }

    const __nv_bfloat16* Bh = g_wth + (size_t)side * 512 * 512;
    const __nv_bfloat16* Bl = g_wtl + (size_t)side * 512 * 512;

    const uint32_t kOff = (lane >> 4) * 16;
    const uint32_t xm   = (lane & 7) << 4;
    const uint32_t aRow = sbase + (uint32_t)(w * 16 + (lane & 15)) * 128;
    const uint32_t bRow = sbase + PJ_B0 + (uint32_t)(lane & 15) * 128;

    float acc[8][4];
#pragma unroll
    for (int j = 0; j < 8; j++)
#pragma unroll
        for (int v = 0; v < 4; v++) acc[j][v] = 0.f;

    // prefetch chunk 0
    {
        uint32_t aB = sbase;
#pragma unroll
        for (int qq = 0; qq < 4; qq++) {
            int idx = qq * 256 + t;
            int row = idx >> 3, seg = idx & 7;
            int rr = m0 + row; rr = rr < Mrows ? rr : Mrows - 1;
            uint32_t d = aB + (((uint32_t)(row * 128 + seg * 16)) ^ ((uint32_t)(row & 7) << 4));
            size_t g = (size_t)(row0_in + rr) * 512 + seg * 8;
            cp16(d, g_inh + g);
            cp16(d + PJ_ALO, g_inl + g);
        }
        uint32_t bB = sbase + PJ_B0;
#pragma unroll
        for (int qq = 0; qq < 2; qq++) {
            int idx = qq * 256 + t;
            int row = idx >> 3, seg = idx & 7;
            uint32_t d = bB + (((uint32_t)(row * 128 + seg * 16)) ^ ((uint32_t)(row & 7) << 4));
            size_t g = (size_t)(j0 + row) * 512 + seg * 8;
            cp16(d, Bh + g);
            cp16(d + PJ_BLO, Bl + g);
        }
        CP_COMMIT();
    }

#pragma unroll 1
    for (int s = 0; s < 8; s++) {
        CP_WAIT0();
        __syncthreads();

        if (s < 7) {
            int kb = (s + 1) * 64;
            uint32_t aB = sbase + (uint32_t)(((s + 1) & 1) * 32768);
#pragma unroll
            for (int qq = 0; qq < 4; qq++) {
                int idx = qq * 256 + t;
                int row = idx >> 3, seg = idx & 7;
                int rr = m0 + row; rr = rr < Mrows ? rr : Mrows - 1;
                uint32_t d = aB + (((uint32_t)(row * 128 + seg * 16)) ^ ((uint32_t)(row & 7) << 4));
                size_t g = (size_t)(row0_in + rr) * 512 + kb + seg * 8;
                cp16(d, g_inh + g);
                cp16(d + PJ_ALO, g_inl + g);
            }
            uint32_t bB = sbase + PJ_B0 + (uint32_t)(((s + 1) & 1) * 16384);
#pragma unroll
            for (int qq = 0; qq < 2; qq++) {
                int idx = qq * 256 + t;
                int row = idx >> 3, seg = idx & 7;
                uint32_t d = bB + (((uint32_t)(row * 128 + seg * 16)) ^ ((uint32_t)(row & 7) << 4));
                size_t g = (size_t)(j0 + row) * 512 + kb + seg * 8;
                cp16(d, Bh + g);
                cp16(d + PJ_BLO, Bl + g);
            }
        }
        CP_COMMIT();

        const uint32_t aHi = aRow + (uint32_t)((s & 1) * 32768);
        const uint32_t bHi = bRow + (uint32_t)((s & 1) * 16384);
#pragma unroll
        for (int ks = 0; ks < 4; ks++) {
            uint32_t ko = ((uint32_t)(ks * 32) + kOff) ^ xm;
            uint32_t ah0, ah1, ah2, ah3, al0, al1, al2, al3;
            ldsm4(ah0, ah1, ah2, ah3, aHi + ko);
            ldsm4(al0, al1, al2, al3, aHi + PJ_ALO + ko);
#pragma unroll
            for (int p = 0; p < 4; p++) {
                uint32_t bh0, bh1, bh2, bh3, bl0, bl1, bl2, bl3;
                uint32_t ba = bHi + (uint32_t)(p * 2048) + ko;
                ldsm4(bh0, bh1, bh2, bh3, ba);
                ldsm4(bl0, bl1, bl2, bl3, ba + PJ_BLO);
                mma16816(acc[2 * p],     ah0, ah1, ah2, ah3, bh0, bh2);
                mma16816(acc[2 * p],     ah0, ah1, ah2, ah3, bl0, bl2);
                mma16816(acc[2 * p],     al0, al1, al2, al3, bh0, bh2);
                mma16816(acc[2 * p + 1], ah0, ah1, ah2, ah3, bh1, bh3);
                mma16816(acc[2 * p + 1], ah0, ah1, ah2, ah3, bl1, bl3);
                mma16816(acc[2 * p + 1], al0, al1, al2, al3, bh1, bh3);
            }
        }
    }

    // epilogue: + bias, split, store
    const int row0 = m0 + w * 16 + (lane >> 2);
    const int row1 = row0 + 8;
    const int colb = (lane & 3) * 2;
#pragma unroll
    for (int j = 0; j < 8; j++) {
        int c = jloc + j * 8 + colb;
        float b0 = bias[c], b1 = bias[c + 1];
        float v0 = acc[j][0] + b0, v1 = acc[j][1] + b1;
        float v2 = acc[j][2] + b0, v3 = acc[j][3] + b1;
        uint32_t h01 = packbf(v0, v1), h23 = packbf(v2, v3);
        uint32_t l01 = packbf(v0 - bf_lo(h01), v1 - bf_hi(h01));
        uint32_t l23 = packbf(v2 - bf_lo(h23), v3 - bf_hi(h23));
        size_t oc = (size_t)j0 + j * 8 + colb;
        if (row0 < Mrows) {
            *(uint32_t*)(ohi + (size_t)row0 * 512 + oc) = h01;
            *(uint32_t*)(olo + (size_t)row0 * 512 + oc) = l01;
        }
        if (row1 < Mrows) {
            *(uint32_t*)(ohi + (size_t)row1 * 512 + oc) = h23;
            *(uint32_t*)(olo + (size_t)row1 * 512 + oc) = l23;
        }
    }
}

// ---------------------------------------------------------------------------
// Fused attention via mma.sync bf16 (split hi/lo, 3-term). Unchanged from R4.
// ---------------------------------------------------------------------------
#define SA_LO 16384u
#define SB0   65536u
#define SB_LO 8192u
#define SVH   98304u
#define SVL   106496u
#define SMEMSZ 114688

__global__ __launch_bounds__(256, 1)
void fused_kernel(const float* __restrict__ vflat)
{
    extern __shared__ char dsm[];
    const uint32_t sbase = smem_u32(dsm);

    const int t    = threadIdx.x;
    const int w    = t >> 5;
    const int lane = t & 31;
    const int m0   = blockIdx.x * 128;
    const int q    = blockIdx.y;
    const int qs0[5] = {0, 7, 14, 21, 27};
    const int jt0 = qs0[q], jt1 = qs0[q + 1];

    const uint32_t kOff = (lane >> 4) * 16;
    const uint32_t xm   = (lane & 7) << 4;
    const uint32_t aRow = sbase + (uint32_t)(w * 16 + (lane & 15)) * 128;
    const uint32_t bRow = sbase + SB0 + (uint32_t)(lane & 15) * 128;
    const uint32_t vRow = sbase + SVH + (uint32_t)(lane & 15) * 128;

    float num[8][4];
#pragma unroll
    for (int j = 0; j < 8; j++)
#pragma unroll
        for (int v = 0; v < 4; v++) num[j][v] = 0.f;
    float den0 = 0.f, den1 = 0.f, off0 = 0.f, off1 = 0.f;

    const float SCALE = 0.25f;
    const float INVH  = 0.08838834764831845f;
    const float SHIFT = 20.0f;

    for (int jt = jt0; jt < jt1; jt++) {
        const int j0 = jt * 64;
        __syncthreads();

        // V^T tile (hi/lo bf16)
#pragma unroll
        for (int qq = 0; qq < 4; qq++) {
            int idx = qq * 256 + t;
            int dom = idx >> 4, c4 = (idx & 15) * 4;
            float4 vv = *(const float4*)(vflat + (size_t)(j0 + dom) * 64 + c4);
            float va[4] = {vv.x, vv.y, vv.z, vv.w};
#pragma unroll
            for (int k = 0; k < 4; k++) {
                int c = c4 + k;
                uint32_t d = (uint32_t)(c * 128 + dom * 2) ^ ((uint32_t)(c & 7) << 4);
                __nv_bfloat16 h = __float2bfloat16_rn(va[k]);
                __nv_bfloat16 l = __float2bfloat16_rn(va[k] - __bfloat162float(h));
                *(__nv_bfloat16*)(dsm + SVH + d) = h;
                *(__nv_bfloat16*)(dsm + SVL + d) = l;
            }
        }

        // prefetch chunk 0
        {
            uint32_t aB = sbase;
#pragma unroll
            for (int qq = 0; qq < 4; qq++) {
                int idx = qq * 256 + t;
                int row = idx >> 3, seg = idx & 7;
                uint32_t d = aB + (((uint32_t)(row * 128 + seg * 16)) ^ ((uint32_t)(row & 7) << 4));
                size_t g = (size_t)(m0 + row) * 512 + seg * 8;
                cp16(d, g_rhi + g);
                cp16(d + SA_LO, g_rlo + g);
            }
            uint32_t bB = sbase + SB0;
#pragma unroll
            for (int qq = 0; qq < 2; qq++) {
                int idx = qq * 256 + t;
                int row = idx >> 3, seg = idx & 7;
                uint32_t d = bB + (((uint32_t)(row * 128 + seg * 16)) ^ ((uint32_t)(row & 7) << 4));
                size_t g = (size_t)(j0 + row) * 512 + seg * 8;
                cp16(d, g_dhi + g);
                cp16(d + SB_LO, g_dlo + g);
            }
            CP_COMMIT();
        }

        float acc[8][4];
#pragma unroll
        for (int j = 0; j < 8; j++)
#pragma unroll
            for (int v = 0; v < 4; v++) acc[j][v] = 0.f;
        float e[8][4];
        uint32_t paH[4][4], paL[4][4];

#pragma unroll 1
        for (int s = 0; s < 8; s++) {
            CP_WAIT0();
            __syncthreads();

            if (s < 7) {
                int sn = s + 1;
                int kb = (sn < 4) ? sn * 64 : ((sn < 6) ? 384 + (sn - 4) * 64
                                                        : 256 + (sn - 6) * 64);
                uint32_t aB = sbase + (uint32_t)((sn & 1) * 32768);
#pragma unroll
                for (int qq = 0; qq < 4; qq++) {
                    int idx = qq * 256 + t;
                    int row = idx >> 3, seg = idx & 7;
                    uint32_t d = aB + (((uint32_t)(row * 128 + seg * 16)) ^ ((uint32_t)(row & 7) << 4));
                    size_t g = (size_t)(m0 + row) * 512 + kb + seg * 8;
                    cp16(d, g_rhi + g);
                    cp16(d + SA_LO, g_rlo + g);
                }
                uint32_t bB = sbase + SB0 + (uint32_t)((sn & 1) * 16384);
#pragma unroll
                for (int qq = 0; qq < 2; qq++) {
                    int idx = qq * 256 + t;
                    int row = idx >> 3, seg = idx & 7;
                    uint32_t d = bB + (((uint32_t)(row * 128 + seg * 16)) ^ ((uint32_t)(row & 7) << 4));
                    size_t g = (size_t)(j0 + row) * 512 + kb + seg * 8;
                    cp16(d, g_dhi + g);
                    cp16(d + SB_LO, g_dlo + g);
                }
            }
            CP_COMMIT();

            const uint32_t aHi = aRow + (uint32_t)((s & 1) * 32768);
            const uint32_t bHi = bRow + (uint32_t)((s & 1) * 16384);
#pragma unroll
            for (int ks = 0; ks < 4; ks++) {
                uint32_t ko = ((uint32_t)(ks * 32) + kOff) ^ xm;
                uint32_t ah0, ah1, ah2, ah3, al0, al1, al2, al3;
                ldsm4(ah0, ah1, ah2, ah3, aHi + ko);
                ldsm4(al0, al1, al2, al3, aHi + SA_LO + ko);
#pragma unroll
                for (int p = 0; p < 4; p++) {
                    uint32_t bh0, bh1, bh2, bh3, bl0, bl1, bl2, bl3;
                    uint32_t ba = bHi + (uint32_t)(p * 2048) + ko;
                    ldsm4(bh0, bh1, bh2, bh3, ba);
                    ldsm4(bl0, bl1, bl2, bl3, ba + SB_LO);
                    mma16816(acc[2 * p],     ah0, ah1, ah2, ah3, bh0, bh2);
                    mma16816(acc[2 * p],     ah0, ah1, ah2, ah3, bl0, bl2);
                    mma16816(acc[2 * p],     al0, al1, al2, al3, bh0, bh2);
                    mma16816(acc[2 * p + 1], ah0, ah1, ah2, ah3, bh1, bh3);
                    mma16816(acc[2 * p + 1], ah0, ah1, ah2, ah3, bl1, bl3);
                    mma16816(acc[2 * p + 1], al0, al1, al2, al3, bh1, bh3);
                }
            }

            if (s == 3) {
#pragma unroll
                for (int j = 0; j < 8; j++) {
#pragma unroll
                    for (int v = 0; v < 4; v++) {
                        e[j][v] = __expf(acc[j][v] * SCALE - SHIFT);
                        acc[j][v] = 0.f;
                    }
                    den0 += e[j][0] + e[j][1];
                    den1 += e[j][2] + e[j][3];
                }
            } else if (s == 5) {
#pragma unroll
                for (int j = 0; j < 8; j++) {
                    off0 += e[j][0] * tanh_fast(acc[j][0] * INVH)
                          + e[j][1] * tanh_fast(acc[j][1] * INVH);
                    off1 += e[j][2] * tanh_fast(acc[j][2] * INVH)
                          + e[j][3] * tanh_fast(acc[j][3] * INVH);
#pragma unroll
                    for (int v = 0; v < 4; v++) acc[j][v] = 0.f;
                }
            } else if (s == 7) {
#pragma unroll
                for (int j = 0; j < 8; j++) {
                    float p0 = e[j][0] * 1.8f * tanh_fast(acc[j][0] * INVH);
                    float p1 = e[j][1] * 1.8f * tanh_fast(acc[j][1] * INVH);
                    float p2 = e[j][2] * 1.8f * tanh_fast(acc[j][2] * INVH);
                    float p3 = e[j][3] * 1.8f * tanh_fast(acc[j][3] * INVH);
                    uint32_t h01 = packbf(p0, p1), h23 = packbf(p2, p3);
                    uint32_t l01 = packbf(p0 - bf_lo(h01), p1 - bf_hi(h01));
                    uint32_t l23 = packbf(p2 - bf_lo(h23), p3 - bf_hi(h23));
                    int kt = j >> 1, ix = (j & 1) * 2;
                    paH[kt][ix] = h01; paH[kt][ix + 1] = h23;
                    paL[kt][ix] = l01; paL[kt][ix + 1] = l23;
                }
            }
        }

        // GEMM2: num += P @ V
#pragma unroll
        for (int kt = 0; kt < 4; kt++) {
            uint32_t ko = ((uint32_t)(kt * 32) + kOff) ^ xm;
#pragma unroll
            for (int p = 0; p < 4; p++) {
                uint32_t vh0, vh1, vh2, vh3, vl0, vl1, vl2, vl3;
                uint32_t va = vRow + (uint32_t)(p * 2048) + ko;
                ldsm4(vh0, vh1, vh2, vh3, va);
                ldsm4(vl0, vl1, vl2, vl3, va + (SVL - SVH));
                mma16816(num[2 * p],     paH[kt][0], paH[kt][1], paH[kt][2], paH[kt][3], vh0, vh2);
                mma16816(num[2 * p],     paH[kt][0], paH[kt][1], paH[kt][2], paH[kt][3], vl0, vl2);
                mma16816(num[2 * p],     paL[kt][0], paL[kt][1], paL[kt][2], paL[kt][3], vh0, vh2);
                mma16816(num[2 * p + 1], paH[kt][0], paH[kt][1], paH[kt][2], paH[kt][3], vh1, vh3);
                mma16816(num[2 * p + 1], paH[kt][0], paH[kt][1], paH[kt][2], paH[kt][3], vl1, vl3);
                mma16816(num[2 * p + 1], paL[kt][0], paL[kt][1], paL[kt][2], paL[kt][3], vh1, vh3);
            }
        }
    }

    const int row0 = m0 + w * 16 + (lane >> 2);
    const int row1 = row0 + 8;
    const int colb = (lane & 3) * 2;
    float* np = g_pnum + (size_t)q * NR * 64;
#pragma unroll
    for (int j = 0; j < 8; j++) {
        *(float2*)(np + (size_t)row0 * 64 + j * 8 + colb) = make_float2(num[j][0], num[j][1]);
        *(float2*)(np + (size_t)row1 * 64 + j * 8 + colb) = make_float2(num[j][2], num[j][3]);
    }
#pragma unroll
    for (int m = 1; m < 4; m <<= 1) {
        den0 += __shfl_xor_sync(0xFFFFFFFFu, den0, m);
        den1 += __shfl_xor_sync(0xFFFFFFFFu, den1, m);
        off0 += __shfl_xor_sync(0xFFFFFFFFu, off0, m);
        off1 += __shfl_xor_sync(0xFFFFFFFFu, off1, m);
    }
    if ((lane & 3) == 0) {
        g_pden[(size_t)q * NR + row0] = den0;
        g_pden[(size_t)q * NR + row1] = den1;
        g_poff[(size_t)q * NR + row0] = off0;
        g_poff[(size_t)q * NR + row1] = off1;
    }
}

// ---------------------------------------------------------------------------
__global__ __launch_bounds__(256) void epilogue_kernel(float* __restrict__ out)
{
    int idx = blockIdx.x * 256 + threadIdx.x;
    if (idx >= NR * 64) return;
    int row = idx >> 6;
    float num = 0.f, den = 0.f, off = 0.f;
#pragma unroll
    for (int q = 0; q < 4; q++) {
        num += g_pnum[(size_t)q * NR * 64 + idx];
        den += g_pden[(size_t)q * NR + row];
        off += g_poff[(size_t)q * NR + row];
    }
    out[idx] = (num + off) / den;
}

// ---------------------------------------------------------------------------
extern "C" void kernel_launch(void* const* d_in, const int* in_sizes, int n_in,
                              void* d_out, int out_size)
{
    (void)in_sizes; (void)n_in; (void)out_size;
    const float* pooled = (const float*)d_in[0];
    const float* rlat   = (const float*)d_in[1];
    const float* dlat   = (const float*)d_in[2];
    const float* rpos   = (const float*)d_in[3];
    const float* dpos   = (const float*)d_in[4];
    const float* Wrp = (const float*)d_in[5];   const float* brp = (const float*)d_in[6];
    const float* Wdp = (const float*)d_in[7];   const float* bdp = (const float*)d_in[8];
    const float* Wrc = (const float*)d_in[9];   const float* brc = (const float*)d_in[10];
    const float* Wdc = (const float*)d_in[11];  const float* bdc = (const float*)d_in[12];
    const float* Wro = (const float*)d_in[13];  const float* bro = (const float*)d_in[14];
    const float* Wdo = (const float*)d_in[15];  const float* bdo = (const float*)d_in[16];
    float* out = (float*)d_out;

    __nv_bfloat16 *rhi, *rlo, *dhi, *dlo;
    cudaGetSymbolAddress((void**)&rhi, g_rhi);
    cudaGetSymbolAddress((void**)&rlo, g_rlo);
    cudaGetSymbolAddress((void**)&dhi, g_dhi);
    cudaGetSymbolAddress((void**)&dlo, g_dlo);

    cudaFuncSetAttribute(fused_kernel,
                         cudaFuncAttributeMaxDynamicSharedMemorySize, SMEMSZ);
    cudaFuncSetAttribute(proj_mma,
                         cudaFuncAttributeMaxDynamicSharedMemorySize, PJ_SMEM);

    prep_w<<<dim3(512, 2), 128>>>(Wrp, Wrc, Wro, Wdp, Wdc, Wdo);
    prep_in<<<(NR * 128 + 255) / 256, 256>>>(rlat, rpos, NR, 0);
    prep_in<<<(ND * 128 + 255) / 256, 256>>>(dlat, dpos, ND, NR);

    proj_mma<<<dim3(108, 8), 256, PJ_SMEM>>>(0, NR, 0, brp, brc, bro, rhi, rlo);
    proj_mma<<<dim3(14, 8), 256, PJ_SMEM>>>(NR, ND, 1, bdp, bdc, bdo, dhi, dlo);

    fused_kernel<<<dim3(108, 4), 256, SMEMSZ>>>(pooled);

    epilogue_kernel<<<(NR * 64 + 255) / 256, 256>>>(out);
}

// round 7
// speedup vs baseline: 3.3837x; 1.0986x over previous
#include <cuda_runtime.h>
#include <cuda_bf16.h>
#include <math.h>
#include <stdint.h>

#define NR 13824
#define ND 1728
#define NTOT (NR + ND)
#define NQ 8

// ---------------------------------------------------------------------------
// PTX helpers (sm_80-era instructions only: valid under compute_100)
// ---------------------------------------------------------------------------
__device__ __forceinline__ uint32_t smem_u32(const void* p) {
    uint32_t a;
    asm("{ .reg .u64 t; cvta.to.shared.u64 t, %1; cvt.u32.u64 %0, t; }"
        : "=r"(a) : "l"(p));
    return a;
}
__device__ __forceinline__ void cp16(uint32_t dst, const void* src) {
    asm volatile("cp.async.cg.shared.global [%0], [%1], 16;"
                 :: "r"(dst), "l"(src) : "memory");
}
#define CP_COMMIT() asm volatile("cp.async.commit_group;" ::: "memory")
#define CP_WAIT0()  asm volatile("cp.async.wait_group 0;" ::: "memory")

__device__ __forceinline__ void ldsm4(uint32_t& r0, uint32_t& r1,
                                      uint32_t& r2, uint32_t& r3, uint32_t a) {
    asm volatile("ldmatrix.sync.aligned.m8n8.x4.shared.b16 {%0,%1,%2,%3}, [%4];"
                 : "=r"(r0), "=r"(r1), "=r"(r2), "=r"(r3) : "r"(a));
}
__device__ __forceinline__ void mma16816(float* c, uint32_t a0, uint32_t a1,
                                         uint32_t a2, uint32_t a3,
                                         uint32_t b0, uint32_t b1) {
    asm volatile(
        "mma.sync.aligned.m16n8k16.row.col.f32.bf16.bf16.f32 "
        "{%0,%1,%2,%3}, {%4,%5,%6,%7}, {%8,%9}, {%0,%1,%2,%3};"
        : "+f"(c[0]), "+f"(c[1]), "+f"(c[2]), "+f"(c[3])
        : "r"(a0), "r"(a1), "r"(a2), "r"(a3), "r"(b0), "r"(b1));
}
__device__ __forceinline__ uint32_t packbf(float lo, float hi) {
    uint32_t r;
    asm("cvt.rn.bf16x2.f32 %0, %1, %2;" : "=r"(r) : "f"(hi), "f"(lo));
    return r;
}
__device__ __forceinline__ float bf_lo(uint32_t u) { return __uint_as_float(u << 16); }
__device__ __forceinline__ float bf_hi(uint32_t u) { return __uint_as_float(u & 0xFFFF0000u); }

__device__ __forceinline__ float tanh_fast(float x) {
    float ax = fabsf(x);
    float s = __expf(-2.f * ax);
    float r = __fdividef(1.f - s, 1.f + s);
    return copysignf(r, x);
}

// ---------------------------------------------------------------------------
// Scratch
// ---------------------------------------------------------------------------
__device__ __align__(256) __nv_bfloat16 g_rhi[NR * 512];
__device__ __align__(256) __nv_bfloat16 g_rlo[NR * 512];
__device__ __align__(256) __nv_bfloat16 g_dhi[ND * 512];
__device__ __align__(256) __nv_bfloat16 g_dlo[ND * 512];
__device__ __align__(256) __nv_bfloat16 g_inh[NTOT * 512];
__device__ __align__(256) __nv_bfloat16 g_inl[NTOT * 512];
__device__ __align__(256) __nv_bfloat16 g_wth[2 * 512 * 512];
__device__ __align__(256) __nv_bfloat16 g_wtl[2 * 512 * 512];
__device__ __align__(256) __nv_bfloat16 g_vth[27 * 4096];   // pre-swizzled V^T hi
__device__ __align__(256) __nv_bfloat16 g_vtl[27 * 4096];   // pre-swizzled V^T lo
__device__ __align__(256) float g_pnum[NQ * NR * 64];
__device__ __align__(256) float g_pden[NQ * NR];
__device__ __align__(256) float g_poff[NQ * NR];

// ---------------------------------------------------------------------------
// prep_in: g_in{h,l}[row0+r][k] = split(lat[r][k] + pos[r][k])
// ---------------------------------------------------------------------------
__global__ __launch_bounds__(256) void prep_in(
    const float* __restrict__ lat, const float* __restrict__ pos,
    int nrows, int row0)
{
    size_t idx = (size_t)blockIdx.x * 256 + threadIdx.x;
    size_t total = (size_t)nrows * 128;
    if (idx >= total) return;
    size_t r = idx >> 7;
    int c4 = (int)(idx & 127) * 4;
    size_t g = r * 512 + c4;
    float4 a = *(const float4*)(lat + g);
    float4 p = *(const float4*)(pos + g);
    float v[4] = {a.x + p.x, a.y + p.y, a.z + p.z, a.w + p.w};
    __nv_bfloat16 h[4], l[4];
#pragma unroll
    for (int j = 0; j < 4; j++) {
        h[j] = __float2bfloat16_rn(v[j]);
        l[j] = __float2bfloat16_rn(v[j] - __bfloat162float(h[j]));
    }
    size_t o = (size_t)(row0 + r) * 512 + c4;
    *(uint2*)(g_inh + o) = *(uint2*)h;
    *(uint2*)(g_inl + o) = *(uint2*)l;
}

// ---------------------------------------------------------------------------
// prep_w: g_wt{h,l}[side][n][k] = split(W[k][n]) for combined [Wp|Wc|Wo]
// ---------------------------------------------------------------------------
__global__ __launch_bounds__(128) void prep_w(
    const float* __restrict__ Wrp, const float* __restrict__ Wrc,
    const float* __restrict__ Wro, const float* __restrict__ Wdp,
    const float* __restrict__ Wdc, const float* __restrict__ Wdo)
{
    const int n    = blockIdx.x;
    const int side = blockIdx.y;
    const int k0   = threadIdx.x * 4;

    const float* W; int width; int nloc;
    if (n < 256)      { W = side ? Wdp : Wrp; width = 256; nloc = n; }
    else if (n < 384) { W = side ? Wdc : Wrc; width = 128; nloc = n - 256; }
    else              { W = side ? Wdo : Wro; width = 128; nloc = n - 384; }

    __nv_bfloat16 h[4], l[4];
#pragma unroll
    for (int j = 0; j < 4; j++) {
        float v = W[(size_t)(k0 + j) * width + nloc];
        h[j] = __float2bfloat16_rn(v);
        l[j] = __float2bfloat16_rn(v - __bfloat162float(h[j]));
    }
    size_t o = (size_t)side * 512 * 512 + (size_t)n * 512 + k0;
    *(uint2*)(g_wth + o) = *(uint2*)h;
    *(uint2*)(g_wtl + o) = *(uint2*)l;
}

// ---------------------------------------------------------------------------
// prep_v: pre-swizzled V^T split tiles. Tile jt holds 64 c-rows x 128B, where
// byte offset d = (c*128 + dom*2) ^ ((c&7)<<4)  (matches smem tile layout).
// ---------------------------------------------------------------------------
__global__ __launch_bounds__(256) void prep_v(const float* __restrict__ vflat)
{
    int idx = blockIdx.x * 256 + threadIdx.x;     // per float4: 1728*16
    if (idx >= 1728 * 16) return;
    int dom_g = idx >> 4;
    int c4 = (idx & 15) * 4;
    int jt = dom_g >> 6, dom = dom_g & 63;
    float4 v = *(const float4*)(vflat + (size_t)dom_g * 64 + c4);
    float va[4] = {v.x, v.y, v.z, v.w};
#pragma unroll
    for (int k = 0; k < 4; k++) {
        int c = c4 + k;
        uint32_t d = (uint32_t)(jt * 8192) +
                     (((uint32_t)(c * 128 + dom * 2)) ^ ((uint32_t)(c & 7) << 4));
        __nv_bfloat16 h = __float2bfloat16_rn(va[k]);
        __nv_bfloat16 l = __float2bfloat16_rn(va[k] - __bfloat162float(h));
        *(__nv_bfloat16*)((char*)g_vth + d) = h;
        *(__nv_bfloat16*)((char*)g_vtl + d) = l;
    }
}

// ---------------------------------------------------------------------------
// proj_mma (merged range+domain): features = in @ W^T[side] + bias, split out.
// grid (122, 8): bx<108 -> range side, else domain side (rows clamped).
// ---------------------------------------------------------------------------
#define PJ_ALO 16384u
#define PJ_B0  65536u
#define PJ_BLO 8192u
#define PJ_SMEM 98304

__global__ __launch_bounds__(256, 2) void proj_mma(
    const float* __restrict__ brp, const float* __restrict__ bdp,
    const float* __restrict__ brc, const float* __restrict__ bdc,
    const float* __restrict__ bro, const float* __restrict__ bdo)
{
    extern __shared__ char dsm[];
    const uint32_t sbase = smem_u32(dsm);

    const int t    = threadIdx.x;
    const int w    = t >> 5;
    const int lane = t & 31;
    const int bx   = blockIdx.x;
    const int j0   = blockIdx.y * 64;

    int side, m0, Mrows, row0_in;
    __nv_bfloat16 *ohi, *olo;
    if (bx < 108) { side = 0; m0 = bx * 128; Mrows = NR; row0_in = 0;
                    ohi = g_rhi; olo = g_rlo; }
    else          { side = 1; m0 = (bx - 108) * 128; Mrows = ND; row0_in = NR;
                    ohi = g_dhi; olo = g_dlo; }

    const float* bias; int jloc;
    if (j0 < 256)      { bias = side ? bdp : brp; jloc = j0; }
    else if (j0 < 384) { bias = side ? bdc : brc; jloc = j0 - 256; }
    else               { bias = side ? bdo : bro; jloc = j0 - 384; }

    const __nv_bfloat16* Bh = g_wth + (size_t)side * 512 * 512;
    const __nv_bfloat16* Bl = g_wtl + (size_t)side * 512 * 512;

    const uint32_t kOff = (lane >> 4) * 16;
    const uint32_t xm   = (lane & 7) << 4;
    const uint32_t aRow = sbase + (uint32_t)(w * 16 + (lane & 15)) * 128;
    const uint32_t bRow = sbase + PJ_B0 + (uint32_t)(lane & 15) * 128;

    float acc[8][4];
#pragma unroll
    for (int j = 0; j < 8; j++)
#pragma unroll
        for (int v = 0; v < 4; v++) acc[j][v] = 0.f;

    auto pre = [&](int kb, int buf) {
        uint32_t aB = sbase + (uint32_t)(buf * 32768);
#pragma unroll
        for (int qq = 0; qq < 4; qq++) {
            int idx = qq * 256 + t;
            int row = idx >> 3, seg = idx & 7;
            int rr = m0 + row; rr = rr < Mrows ? rr : Mrows - 1;
            uint32_t d = aB + (((uint32_t)(row * 128 + seg * 16)) ^ ((uint32_t)(row & 7) << 4));
            size_t g = (size_t)(row0_in + rr) * 512 + kb + seg * 8;
            cp16(d, g_inh + g);
            cp16(d + PJ_ALO, g_inl + g);
        }
        uint32_t bB = sbase + PJ_B0 + (uint32_t)(buf * 16384);
#pragma unroll
        for (int qq = 0; qq < 2; qq++) {
            int idx = qq * 256 + t;
            int row = idx >> 3, seg = idx & 7;
            uint32_t d = bB + (((uint32_t)(row * 128 + seg * 16)) ^ ((uint32_t)(row & 7) << 4));
            size_t g = (size_t)(j0 + row) * 512 + kb + seg * 8;
            cp16(d, Bh + g);
            cp16(d + PJ_BLO, Bl + g);
        }
    };

    pre(0, 0);
    CP_COMMIT();

#pragma unroll 1
    for (int s = 0; s < 8; s++) {
        CP_WAIT0();
        __syncthreads();
        if (s < 7) pre((s + 1) * 64, (s + 1) & 1);
        CP_COMMIT();

        const uint32_t aHi = aRow + (uint32_t)((s & 1) * 32768);
        const uint32_t bHi = bRow + (uint32_t)((s & 1) * 16384);
#pragma unroll
        for (int ks = 0; ks < 4; ks++) {
            uint32_t ko = ((uint32_t)(ks * 32) + kOff) ^ xm;
            uint32_t ah0, ah1, ah2, ah3, al0, al1, al2, al3;
            ldsm4(ah0, ah1, ah2, ah3, aHi + ko);
            ldsm4(al0, al1, al2, al3, aHi + PJ_ALO + ko);
#pragma unroll
            for (int p = 0; p < 4; p++) {
                uint32_t bh0, bh1, bh2, bh3, bl0, bl1, bl2, bl3;
                uint32_t ba = bHi + (uint32_t)(p * 2048) + ko;
                ldsm4(bh0, bh1, bh2, bh3, ba);
                ldsm4(bl0, bl1, bl2, bl3, ba + PJ_BLO);
                mma16816(acc[2 * p],     ah0, ah1, ah2, ah3, bh0, bh2);
                mma16816(acc[2 * p],     ah0, ah1, ah2, ah3, bl0, bl2);
                mma16816(acc[2 * p],     al0, al1, al2, al3, bh0, bh2);
                mma16816(acc[2 * p + 1], ah0, ah1, ah2, ah3, bh1, bh3);
                mma16816(acc[2 * p + 1], ah0, ah1, ah2, ah3, bl1, bl3);
                mma16816(acc[2 * p + 1], al0, al1, al2, al3, bh1, bh3);
            }
        }
    }

    const int row0 = m0 + w * 16 + (lane >> 2);
    const int row1 = row0 + 8;
    const int colb = (lane & 3) * 2;
#pragma unroll
    for (int j = 0; j < 8; j++) {
        int c = jloc + j * 8 + colb;
        float b0 = bias[c], b1 = bias[c + 1];
        float v0 = acc[j][0] + b0, v1 = acc[j][1] + b1;
        float v2 = acc[j][2] + b0, v3 = acc[j][3] + b1;
        uint32_t h01 = packbf(v0, v1), h23 = packbf(v2, v3);
        uint32_t l01 = packbf(v0 - bf_lo(h01), v1 - bf_hi(h01));
        uint32_t l23 = packbf(v2 - bf_lo(h23), v3 - bf_hi(h23));
        size_t oc = (size_t)j0 + j * 8 + colb;
        if (row0 < Mrows) {
            *(uint32_t*)(ohi + (size_t)row0 * 512 + oc) = h01;
            *(uint32_t*)(olo + (size_t)row0 * 512 + oc) = l01;
        }
        if (row1 < Mrows) {
            *(uint32_t*)(ohi + (size_t)row1 * 512 + oc) = h23;
            *(uint32_t*)(olo + (size_t)row1 * 512 + oc) = l23;
        }
    }
}

// ---------------------------------------------------------------------------
// Fused attention. 2 CTAs/SM target: P routed through the chunk-7 A buffer
// (no paH/paL register arrays), V^T pre-swizzled in global. 864 CTAs (108 x 8).
// smem: A bufs 64KB @0 (buf1 hi @32768, lo @49152), B bufs 32KB @65536,
// V 16KB @98304 -> 112KB.
// Chunk order: s0-3 logits (k 0..255), s4-5 offset (k 384..511),
// s6-7 contrast (k 256..383).
// ---------------------------------------------------------------------------
#define SA_LO 16384u
#define SB0   65536u
#define SB_LO 8192u
#define SVH   98304u
#define SMEMSZ 114688

__global__ __launch_bounds__(256, 2)
void fused_kernel()
{
    extern __shared__ char dsm[];
    const uint32_t sbase = smem_u32(dsm);

    const int t    = threadIdx.x;
    const int w    = t >> 5;
    const int lane = t & 31;
    const int m0   = blockIdx.x * 128;
    const int q    = blockIdx.y;
    const int qs0[NQ + 1] = {0, 4, 8, 12, 15, 18, 21, 24, 27};
    const int jt0 = qs0[q], jt1 = qs0[q + 1];

    const uint32_t kOff = (lane >> 4) * 16;
    const uint32_t xm   = (lane & 7) << 4;
    const uint32_t aRow = sbase + (uint32_t)(w * 16 + (lane & 15)) * 128;
    const uint32_t bRow = sbase + SB0 + (uint32_t)(lane & 15) * 128;
    const uint32_t vRow = sbase + SVH + (uint32_t)(lane & 15) * 128;
    const uint32_t pRow = sbase + 32768u + (uint32_t)(w * 16 + (lane & 15)) * 128;

    float num[8][4];
#pragma unroll
    for (int j = 0; j < 8; j++)
#pragma unroll
        for (int v = 0; v < 4; v++) num[j][v] = 0.f;
    float den0 = 0.f, den1 = 0.f, off0 = 0.f, off1 = 0.f;

    const float SCALE = 0.25f;
    const float INVH  = 0.08838834764831845f;
    const float SHIFT = 20.0f;

    auto pre_a = [&](int kb, int buf) {
        uint32_t aB = sbase + (uint32_t)(buf * 32768);
#pragma unroll
        for (int qq = 0; qq < 4; qq++) {
            int idx = qq * 256 + t;
            int row = idx >> 3, seg = idx & 7;
            uint32_t d = aB + (((uint32_t)(row * 128 + seg * 16)) ^ ((uint32_t)(row & 7) << 4));
            size_t g = (size_t)(m0 + row) * 512 + kb + seg * 8;
            cp16(d, g_rhi + g);
            cp16(d + SA_LO, g_rlo + g);
        }
    };
    auto pre_b = [&](int j0c, int kb, int buf) {
        uint32_t bB = sbase + SB0 + (uint32_t)(buf * 16384);
#pragma unroll
        for (int qq = 0; qq < 2; qq++) {
            int idx = qq * 256 + t;
            int row = idx >> 3, seg = idx & 7;
            uint32_t d = bB + (((uint32_t)(row * 128 + seg * 16)) ^ ((uint32_t)(row & 7) << 4));
            size_t g = (size_t)(j0c + row) * 512 + kb + seg * 8;
            cp16(d, g_dhi + g);
            cp16(d + SB_LO, g_dlo + g);
        }
    };
    auto pre_v = [&](int jt) {
        const char* srcH = (const char*)g_vth + (size_t)jt * 8192;
        const char* srcL = (const char*)g_vtl + (size_t)jt * 8192;
#pragma unroll
        for (int qq = 0; qq < 2; qq++) {
            int idx = qq * 256 + t;
            cp16(sbase + SVH + (uint32_t)(idx * 16), srcH + idx * 16);
            cp16(sbase + SVH + 8192u + (uint32_t)(idx * 16), srcL + idx * 16);
        }
    };

    // initial prefetch: chunk0 + V of first tile
    pre_a(0, 0);
    pre_b(jt0 * 64, 0, 0);
    pre_v(jt0);
    CP_COMMIT();

#pragma unroll 1
    for (int jt = jt0; jt < jt1; jt++) {
        const int j0 = jt * 64;

        float acc[8][4];
#pragma unroll
        for (int j = 0; j < 8; j++)
#pragma unroll
            for (int v = 0; v < 4; v++) acc[j][v] = 0.f;
        float e[8][4];

#pragma unroll 1
        for (int s = 0; s < 8; s++) {
            CP_WAIT0();
            __syncthreads();

            if (s < 7) {
                int sn = s + 1;
                int kb = (sn < 4) ? sn * 64 : ((sn < 6) ? 384 + (sn - 4) * 64
                                                        : 256 + (sn - 6) * 64);
                pre_a(kb, sn & 1);
                pre_b(j0, kb, sn & 1);
                CP_COMMIT();
            } else if (jt + 1 < jt1) {
                pre_a(0, 0);
                pre_b((jt + 1) * 64, 0, 0);
                CP_COMMIT();
            }

            const uint32_t aHi = aRow + (uint32_t)((s & 1) * 32768);
            const uint32_t bHi = bRow + (uint32_t)((s & 1) * 16384);
#pragma unroll
            for (int ks = 0; ks < 4; ks++) {
                uint32_t ko = ((uint32_t)(ks * 32) + kOff) ^ xm;
                uint32_t ah0, ah1, ah2, ah3, al0, al1, al2, al3;
                ldsm4(ah0, ah1, ah2, ah3, aHi + ko);
                ldsm4(al0, al1, al2, al3, aHi + SA_LO + ko);
#pragma unroll
                for (int p = 0; p < 4; p++) {
                    uint32_t bh0, bh1, bh2, bh3, bl0, bl1, bl2, bl3;
                    uint32_t ba = bHi + (uint32_t)(p * 2048) + ko;
                    ldsm4(bh0, bh1, bh2, bh3, ba);
                    ldsm4(bl0, bl1, bl2, bl3, ba + SB_LO);
                    mma16816(acc[2 * p],     ah0, ah1, ah2, ah3, bh0, bh2);
                    mma16816(acc[2 * p],     ah0, ah1, ah2, ah3, bl0, bl2);
                    mma16816(acc[2 * p],     al0, al1, al2, al3, bh0, bh2);
                    mma16816(acc[2 * p + 1], ah0, ah1, ah2, ah3, bh1, bh3);
                    mma16816(acc[2 * p + 1], ah0, ah1, ah2, ah3, bl1, bl3);
                    mma16816(acc[2 * p + 1], al0, al1, al2, al3, bh1, bh3);
                }
            }

            if (s == 3) {                 // logits -> e, den
#pragma unroll
                for (int j = 0; j < 8; j++) {
#pragma unroll
                    for (int v = 0; v < 4; v++) {
                        e[j][v] = __expf(acc[j][v] * SCALE - SHIFT);
                        acc[j][v] = 0.f;
                    }
                    den0 += e[j][0] + e[j][1];
                    den1 += e[j][2] + e[j][3];
                }
            } else if (s == 5) {          // offset section done
#pragma unroll
                for (int j = 0; j < 8; j++) {
                    off0 += e[j][0] * tanh_fast(acc[j][0] * INVH)
                          + e[j][1] * tanh_fast(acc[j][1] * INVH);
                    off1 += e[j][2] * tanh_fast(acc[j][2] * INVH)
                          + e[j][3] * tanh_fast(acc[j][3] * INVH);
#pragma unroll
                    for (int v = 0; v < 4; v++) acc[j][v] = 0.f;
                }
            }
        }

        // ---- P = e * 1.8 * tanh(con) -> chunk-7 A buffer (buf1), hi/lo ----
        __syncthreads();   // all chunk-7 ldsm complete
        {
            char* pPh = dsm + 32768;
            char* pPl = dsm + 49152;
            const int r0 = w * 16 + (lane >> 2);
            const int r1 = r0 + 8;
            const int colb = (lane & 3) * 2;
#pragma unroll
            for (int j = 0; j < 8; j++) {
                float p0 = e[j][0] * 1.8f * tanh_fast(acc[j][0] * INVH);
                float p1 = e[j][1] * 1.8f * tanh_fast(acc[j][1] * INVH);
                float p2 = e[j][2] * 1.8f * tanh_fast(acc[j][2] * INVH);
                float p3 = e[j][3] * 1.8f * tanh_fast(acc[j][3] * INVH);
                uint32_t h01 = packbf(p0, p1), h23 = packbf(p2, p3);
                uint32_t l01 = packbf(p0 - bf_lo(h01), p1 - bf_hi(h01));
                uint32_t l23 = packbf(p2 - bf_lo(h23), p3 - bf_hi(h23));
                int c = j * 8 + colb;
                uint32_t d0 = ((uint32_t)(r0 * 128 + c * 2)) ^ ((uint32_t)(r0 & 7) << 4);
                uint32_t d1 = ((uint32_t)(r1 * 128 + c * 2)) ^ ((uint32_t)(r1 & 7) << 4);
                *(uint32_t*)(pPh + d0) = h01;
                *(uint32_t*)(pPl + d0) = l01;
                *(uint32_t*)(pPh + d1) = h23;
                *(uint32_t*)(pPl + d1) = l23;
            }
        }
        __syncthreads();

        // ---- GEMM2: num += P @ V ----
#pragma unroll
        for (int kt = 0; kt < 4; kt++) {
            uint32_t ko = ((uint32_t)(kt * 32) + kOff) ^ xm;
            uint32_t ph0, ph1, ph2, ph3, pl0, pl1, pl2, pl3;
            ldsm4(ph0, ph1, ph2, ph3, pRow + ko);
            ldsm4(pl0, pl1, pl2, pl3, pRow + SA_LO + ko);
#pragma unroll
            for (int p = 0; p < 4; p++) {
                uint32_t vh0, vh1, vh2, vh3, vl0, vl1, vl2, vl3;
                uint32_t va = vRow + (uint32_t)(p * 2048) + ko;
                ldsm4(vh0, vh1, vh2, vh3, va);
                ldsm4(vl0, vl1, vl2, vl3, va + 8192u);
                mma16816(num[2 * p],     ph0, ph1, ph2, ph3, vh0, vh2);
                mma16816(num[2 * p],     ph0, ph1, ph2, ph3, vl0, vl2);
                mma16816(num[2 * p],     pl0, pl1, pl2, pl3, vh0, vh2);
                mma16816(num[2 * p + 1], ph0, ph1, ph2, ph3, vh1, vh3);
                mma16816(num[2 * p + 1], ph0, ph1, ph2, ph3, vl1, vl3);
                mma16816(num[2 * p + 1], pl0, pl1, pl2, pl3, vh1, vh3);
            }
        }
        __syncthreads();   // V + P buffer free before next tile overwrites

        if (jt + 1 < jt1) {
            pre_v(jt + 1);
            CP_COMMIT();
        }
    }

    // ---- write partials ----
    const int row0 = m0 + w * 16 + (lane >> 2);
    const int row1 = row0 + 8;
    const int colb = (lane & 3) * 2;
    float* np = g_pnum + (size_t)q * NR * 64;
#pragma unroll
    for (int j = 0; j < 8; j++) {
        *(float2*)(np + (size_t)row0 * 64 + j * 8 + colb) = make_float2(num[j][0], num[j][1]);
        *(float2*)(np + (size_t)row1 * 64 + j * 8 + colb) = make_float2(num[j][2], num[j][3]);
    }
#pragma unroll
    for (int m = 1; m < 4; m <<= 1) {
        den0 += __shfl_xor_sync(0xFFFFFFFFu, den0, m);
        den1 += __shfl_xor_sync(0xFFFFFFFFu, den1, m);
        off0 += __shfl_xor_sync(0xFFFFFFFFu, off0, m);
        off1 += __shfl_xor_sync(0xFFFFFFFFu, off1, m);
    }
    if ((lane & 3) == 0) {
        g_pden[(size_t)q * NR + row0] = den0;
        g_pden[(size_t)q * NR + row1] = den1;
        g_poff[(size_t)q * NR + row0] = off0;
        g_poff[(size_t)q * NR + row1] = off1;
    }
}

// ---------------------------------------------------------------------------
__global__ __launch_bounds__(256) void epilogue_kernel(float* __restrict__ out)
{
    int idx = blockIdx.x * 256 + threadIdx.x;
    if (idx >= NR * 64) return;
    int row = idx >> 6;
    float num = 0.f, den = 0.f, off = 0.f;
#pragma unroll
    for (int q = 0; q < NQ; q++) {
        num += g_pnum[(size_t)q * NR * 64 + idx];
        den += g_pden[(size_t)q * NR + row];
        off += g_poff[(size_t)q * NR + row];
    }
    out[idx] = (num + off) / den;
}

// ---------------------------------------------------------------------------
extern "C" void kernel_launch(void* const* d_in, const int* in_sizes, int n_in,
                              void* d_out, int out_size)
{
    (void)in_sizes; (void)n_in; (void)out_size;
    const float* pooled = (const float*)d_in[0];
    const float* rlat   = (const float*)d_in[1];
    const float* dlat   = (const float*)d_in[2];
    const float* rpos   = (const float*)d_in[3];
    const float* dpos   = (const float*)d_in[4];
    const float* Wrp = (const float*)d_in[5];   const float* brp = (const float*)d_in[6];
    const float* Wdp = (const float*)d_in[7];   const float* bdp = (const float*)d_in[8];
    const float* Wrc = (const float*)d_in[9];   const float* brc = (const float*)d_in[10];
    const float* Wdc = (const float*)d_in[11];  const float* bdc = (const float*)d_in[12];
    const float* Wro = (const float*)d_in[13];  const float* bro = (const float*)d_in[14];
    const float* Wdo = (const float*)d_in[15];  const float* bdo = (const float*)d_in[16];
    float* out = (float*)d_out;

    cudaFuncSetAttribute(fused_kernel,
                         cudaFuncAttributeMaxDynamicSharedMemorySize, SMEMSZ);
    cudaFuncSetAttribute(proj_mma,
                         cudaFuncAttributeMaxDynamicSharedMemorySize, PJ_SMEM);

    prep_w<<<dim3(512, 2), 128>>>(Wrp, Wrc, Wro, Wdp, Wdc, Wdo);
    prep_in<<<(NR * 128 + 255) / 256, 256>>>(rlat, rpos, NR, 0);
    prep_in<<<(ND * 128 + 255) / 256, 256>>>(dlat, dpos, ND, NR);
    prep_v<<<108, 256>>>(pooled);

    proj_mma<<<dim3(122, 8), 256, PJ_SMEM>>>(brp, bdp, brc, bdc, bro, bdo);

    fused_kernel<<<dim3(108, NQ), 256, SMEMSZ>>>();

    epilogue_kernel<<<(NR * 64 + 255) / 256, 256>>>(out);
}

// round 8
// speedup vs baseline: 3.4129x; 1.0086x over previous
#include <cuda_runtime.h>
#include <cuda_bf16.h>
#include <math.h>
#include <stdint.h>

#define NR 13824
#define ND 1728
#define NTOT (NR + ND)
#define NQ 8

// ---------------------------------------------------------------------------
// PTX helpers (sm_80-era instructions only: valid under compute_100)
// ---------------------------------------------------------------------------
__device__ __forceinline__ uint32_t smem_u32(const void* p) {
    uint32_t a;
    asm("{ .reg .u64 t; cvta.to.shared.u64 t, %1; cvt.u32.u64 %0, t; }"
        : "=r"(a) : "l"(p));
    return a;
}
__device__ __forceinline__ void cp16(uint32_t dst, const void* src) {
    asm volatile("cp.async.cg.shared.global [%0], [%1], 16;"
                 :: "r"(dst), "l"(src) : "memory");
}
#define CP_COMMIT() asm volatile("cp.async.commit_group;" ::: "memory")
#define CP_WAIT0()  asm volatile("cp.async.wait_group 0;" ::: "memory")

__device__ __forceinline__ void ldsm4(uint32_t& r0, uint32_t& r1,
                                      uint32_t& r2, uint32_t& r3, uint32_t a) {
    asm volatile("ldmatrix.sync.aligned.m8n8.x4.shared.b16 {%0,%1,%2,%3}, [%4];"
                 : "=r"(r0), "=r"(r1), "=r"(r2), "=r"(r3) : "r"(a));
}
__device__ __forceinline__ void mma16816(float* c, const uint32_t* a,
                                         uint32_t b0, uint32_t b1) {
    asm volatile(
        "mma.sync.aligned.m16n8k16.row.col.f32.bf16.bf16.f32 "
        "{%0,%1,%2,%3}, {%4,%5,%6,%7}, {%8,%9}, {%0,%1,%2,%3};"
        : "+f"(c[0]), "+f"(c[1]), "+f"(c[2]), "+f"(c[3])
        : "r"(a[0]), "r"(a[1]), "r"(a[2]), "r"(a[3]), "r"(b0), "r"(b1));
}
__device__ __forceinline__ uint32_t packbf(float lo, float hi) {
    uint32_t r;
    asm("cvt.rn.bf16x2.f32 %0, %1, %2;" : "=r"(r) : "f"(hi), "f"(lo));
    return r;
}
__device__ __forceinline__ float bf_lo(uint32_t u) { return __uint_as_float(u << 16); }
__device__ __forceinline__ float bf_hi(uint32_t u) { return __uint_as_float(u & 0xFFFF0000u); }

__device__ __forceinline__ float tanh_fast(float x) {
    float ax = fabsf(x);
    float s = __expf(-2.f * ax);
    float r = __fdividef(1.f - s, 1.f + s);
    return copysignf(r, x);
}

// ---------------------------------------------------------------------------
// Scratch
// ---------------------------------------------------------------------------
__device__ __align__(256) __nv_bfloat16 g_rhi[NR * 512];
__device__ __align__(256) __nv_bfloat16 g_rlo[NR * 512];
__device__ __align__(256) __nv_bfloat16 g_dhi[ND * 512];
__device__ __align__(256) __nv_bfloat16 g_dlo[ND * 512];
__device__ __align__(256) __nv_bfloat16 g_inh[NTOT * 512];
__device__ __align__(256) __nv_bfloat16 g_inl[NTOT * 512];
__device__ __align__(256) __nv_bfloat16 g_wth[2 * 512 * 512];
__device__ __align__(256) __nv_bfloat16 g_wtl[2 * 512 * 512];
__device__ __align__(256) __nv_bfloat16 g_vth[27 * 4096];
__device__ __align__(256) __nv_bfloat16 g_vtl[27 * 4096];
__device__ __align__(256) float g_pnum[NQ * NR * 64];
__device__ __align__(256) float g_pden[NQ * NR];
__device__ __align__(256) float g_poff[NQ * NR];

// ---------------------------------------------------------------------------
__global__ __launch_bounds__(256) void prep_in(
    const float* __restrict__ lat, const float* __restrict__ pos,
    int nrows, int row0)
{
    size_t idx = (size_t)blockIdx.x * 256 + threadIdx.x;
    size_t total = (size_t)nrows * 128;
    if (idx >= total) return;
    size_t r = idx >> 7;
    int c4 = (int)(idx & 127) * 4;
    size_t g = r * 512 + c4;
    float4 a = *(const float4*)(lat + g);
    float4 p = *(const float4*)(pos + g);
    float v[4] = {a.x + p.x, a.y + p.y, a.z + p.z, a.w + p.w};
    __nv_bfloat16 h[4], l[4];
#pragma unroll
    for (int j = 0; j < 4; j++) {
        h[j] = __float2bfloat16_rn(v[j]);
        l[j] = __float2bfloat16_rn(v[j] - __bfloat162float(h[j]));
    }
    size_t o = (size_t)(row0 + r) * 512 + c4;
    *(uint2*)(g_inh + o) = *(uint2*)h;
    *(uint2*)(g_inl + o) = *(uint2*)l;
}

// ---------------------------------------------------------------------------
__global__ __launch_bounds__(128) void prep_w(
    const float* __restrict__ Wrp, const float* __restrict__ Wrc,
    const float* __restrict__ Wro, const float* __restrict__ Wdp,
    const float* __restrict__ Wdc, const float* __restrict__ Wdo)
{
    const int n    = blockIdx.x;
    const int side = blockIdx.y;
    const int k0   = threadIdx.x * 4;

    const float* W; int width; int nloc;
    if (n < 256)      { W = side ? Wdp : Wrp; width = 256; nloc = n; }
    else if (n < 384) { W = side ? Wdc : Wrc; width = 128; nloc = n - 256; }
    else              { W = side ? Wdo : Wro; width = 128; nloc = n - 384; }

    __nv_bfloat16 h[4], l[4];
#pragma unroll
    for (int j = 0; j < 4; j++) {
        float v = W[(size_t)(k0 + j) * width + nloc];
        h[j] = __float2bfloat16_rn(v);
        l[j] = __float2bfloat16_rn(v - __bfloat162float(h[j]));
    }
    size_t o = (size_t)side * 512 * 512 + (size_t)n * 512 + k0;
    *(uint2*)(g_wth + o) = *(uint2*)h;
    *(uint2*)(g_wtl + o) = *(uint2*)l;
}

// ---------------------------------------------------------------------------
__global__ __launch_bounds__(256) void prep_v(const float* __restrict__ vflat)
{
    int idx = blockIdx.x * 256 + threadIdx.x;
    if (idx >= 1728 * 16) return;
    int dom_g = idx >> 4;
    int c4 = (idx & 15) * 4;
    int jt = dom_g >> 6, dom = dom_g & 63;
    float4 v = *(const float4*)(vflat + (size_t)dom_g * 64 + c4);
    float va[4] = {v.x, v.y, v.z, v.w};
#pragma unroll
    for (int k = 0; k < 4; k++) {
        int c = c4 + k;
        uint32_t d = (uint32_t)(jt * 8192) +
                     (((uint32_t)(c * 128 + dom * 2)) ^ ((uint32_t)(c & 7) << 4));
        __nv_bfloat16 h = __float2bfloat16_rn(va[k]);
        __nv_bfloat16 l = __float2bfloat16_rn(va[k] - __bfloat162float(h));
        *(__nv_bfloat16*)((char*)g_vth + d) = h;
        *(__nv_bfloat16*)((char*)g_vtl + d) = l;
    }
}

// ---------------------------------------------------------------------------
// proj_mma: 32x32 warp tiles (4 row-groups x 2 col-groups).
// ---------------------------------------------------------------------------
#define PJ_ALO 16384u
#define PJ_B0  65536u
#define PJ_BLO 8192u
#define PJ_SMEM 98304

__global__ __launch_bounds__(256, 2) void proj_mma(
    const float* __restrict__ brp, const float* __restrict__ bdp,
    const float* __restrict__ brc, const float* __restrict__ bdc,
    const float* __restrict__ bro, const float* __restrict__ bdo)
{
    extern __shared__ char dsm[];
    const uint32_t sbase = smem_u32(dsm);

    const int t    = threadIdx.x;
    const int w    = t >> 5;
    const int lane = t & 31;
    const int bx   = blockIdx.x;
    const int j0   = blockIdx.y * 64;

    int side, m0, Mrows, row0_in;
    __nv_bfloat16 *ohi, *olo;
    if (bx < 108) { side = 0; m0 = bx * 128; Mrows = NR; row0_in = 0;
                    ohi = g_rhi; olo = g_rlo; }
    else          { side = 1; m0 = (bx - 108) * 128; Mrows = ND; row0_in = NR;
                    ohi = g_dhi; olo = g_dlo; }

    const float* bias; int jloc;
    if (j0 < 256)      { bias = side ? bdp : brp; jloc = j0; }
    else if (j0 < 384) { bias = side ? bdc : brc; jloc = j0 - 256; }
    else               { bias = side ? bdo : bro; jloc = j0 - 384; }

    const __nv_bfloat16* Bh = g_wth + (size_t)side * 512 * 512;
    const __nv_bfloat16* Bl = g_wtl + (size_t)side * 512 * 512;

    const int wrow = (w >> 1) * 32;
    const int wcol = (w & 1) * 32;
    const uint32_t kOff = (lane >> 4) * 16;
    const uint32_t xm   = (lane & 7) << 4;
    const uint32_t aRow = sbase + (uint32_t)(wrow + (lane & 15)) * 128;
    const uint32_t bRow = sbase + PJ_B0 + (uint32_t)(wcol + (lane & 15)) * 128;

    float acc[8][4];
#pragma unroll
    for (int j = 0; j < 8; j++)
#pragma unroll
        for (int v = 0; v < 4; v++) acc[j][v] = 0.f;

    auto pre = [&](int kb, int buf) {
        uint32_t aB = sbase + (uint32_t)(buf * 32768);
#pragma unroll
        for (int qq = 0; qq < 4; qq++) {
            int idx = qq * 256 + t;
            int row = idx >> 3, seg = idx & 7;
            int rr = m0 + row; rr = rr < Mrows ? rr : Mrows - 1;
            uint32_t d = aB + (((uint32_t)(row * 128 + seg * 16)) ^ ((uint32_t)(row & 7) << 4));
            size_t g = (size_t)(row0_in + rr) * 512 + kb + seg * 8;
            cp16(d, g_inh + g);
            cp16(d + PJ_ALO, g_inl + g);
        }
        uint32_t bB = sbase + PJ_B0 + (uint32_t)(buf * 16384);
#pragma unroll
        for (int qq = 0; qq < 2; qq++) {
            int idx = qq * 256 + t;
            int row = idx >> 3, seg = idx & 7;
            uint32_t d = bB + (((uint32_t)(row * 128 + seg * 16)) ^ ((uint32_t)(row & 7) << 4));
            size_t g = (size_t)(j0 + row) * 512 + kb + seg * 8;
            cp16(d, Bh + g);
            cp16(d + PJ_BLO, Bl + g);
        }
    };

    pre(0, 0);
    CP_COMMIT();

#pragma unroll 1
    for (int s = 0; s < 8; s++) {
        CP_WAIT0();
        __syncthreads();
        if (s < 7) pre((s + 1) * 64, (s + 1) & 1);
        CP_COMMIT();

        const uint32_t aHi = aRow + (uint32_t)((s & 1) * 32768);
        const uint32_t bHi = bRow + (uint32_t)((s & 1) * 16384);
#pragma unroll
        for (int ks = 0; ks < 4; ks++) {
            uint32_t ko = ((uint32_t)(ks * 32) + kOff) ^ xm;
            uint32_t ah0[4], ah1[4], al0[4], al1[4];
            ldsm4(ah0[0], ah0[1], ah0[2], ah0[3], aHi + ko);
            ldsm4(ah1[0], ah1[1], ah1[2], ah1[3], aHi + 2048u + ko);
            ldsm4(al0[0], al0[1], al0[2], al0[3], aHi + PJ_ALO + ko);
            ldsm4(al1[0], al1[1], al1[2], al1[3], aHi + PJ_ALO + 2048u + ko);
#pragma unroll
            for (int nb = 0; nb < 2; nb++) {
                uint32_t bh0, bh1, bh2, bh3, bl0, bl1, bl2, bl3;
                uint32_t ba = bHi + (uint32_t)(nb * 2048) + ko;
                ldsm4(bh0, bh1, bh2, bh3, ba);
                ldsm4(bl0, bl1, bl2, bl3, ba + PJ_BLO);
                mma16816(acc[nb * 2],     ah0, bh0, bh2);
                mma16816(acc[nb * 2],     ah0, bl0, bl2);
                mma16816(acc[nb * 2],     al0, bh0, bh2);
                mma16816(acc[nb * 2 + 1], ah0, bh1, bh3);
                mma16816(acc[nb * 2 + 1], ah0, bl1, bl3);
                mma16816(acc[nb * 2 + 1], al0, bh1, bh3);
                mma16816(acc[4 + nb * 2],     ah1, bh0, bh2);
                mma16816(acc[4 + nb * 2],     ah1, bl0, bl2);
                mma16816(acc[4 + nb * 2],     al1, bh0, bh2);
                mma16816(acc[4 + nb * 2 + 1], ah1, bh1, bh3);
                mma16816(acc[4 + nb * 2 + 1], ah1, bl1, bl3);
                mma16816(acc[4 + nb * 2 + 1], al1, bh1, bh3);
            }
        }
    }

    const int colb = (lane & 3) * 2;
#pragma unroll
    for (int j = 0; j < 8; j++) {
        int m2 = j >> 2;
        int cc = wcol + (j & 3) * 8 + colb;
        int row0 = m0 + wrow + m2 * 16 + (lane >> 2);
        int row1 = row0 + 8;
        int c = jloc + cc;
        float b0 = bias[c], b1 = bias[c + 1];
        float v0 = acc[j][0] + b0, v1 = acc[j][1] + b1;
        float v2 = acc[j][2] + b0, v3 = acc[j][3] + b1;
        uint32_t h01 = packbf(v0, v1), h23 = packbf(v2, v3);
        uint32_t l01 = packbf(v0 - bf_lo(h01), v1 - bf_hi(h01));
        uint32_t l23 = packbf(v2 - bf_lo(h23), v3 - bf_hi(h23));
        size_t oc = (size_t)j0 + cc;
        if (row0 < Mrows) {
            *(uint32_t*)(ohi + (size_t)row0 * 512 + oc) = h01;
            *(uint32_t*)(olo + (size_t)row0 * 512 + oc) = l01;
        }
        if (row1 < Mrows) {
            *(uint32_t*)(ohi + (size_t)row1 * 512 + oc) = h23;
            *(uint32_t*)(olo + (size_t)row1 * 512 + oc) = l23;
        }
    }
}

// ---------------------------------------------------------------------------
// Fused attention, 32x32 warp tiles. Same buffers/schedule as R7.
// ---------------------------------------------------------------------------
#define SA_LO 16384u
#define SB0   65536u
#define SB_LO 8192u
#define SVH   98304u
#define SMEMSZ 114688

__global__ __launch_bounds__(256, 2)
void fused_kernel()
{
    extern __shared__ char dsm[];
    const uint32_t sbase = smem_u32(dsm);

    const int t    = threadIdx.x;
    const int w    = t >> 5;
    const int lane = t & 31;
    const int m0   = blockIdx.x * 128;
    const int q    = blockIdx.y;
    const int qs0[NQ + 1] = {0, 4, 8, 12, 15, 18, 21, 24, 27};
    const int jt0 = qs0[q], jt1 = qs0[q + 1];

    const int wrow = (w >> 1) * 32;
    const int wcol = (w & 1) * 32;
    const uint32_t kOff = (lane >> 4) * 16;
    const uint32_t xm   = (lane & 7) << 4;
    const uint32_t aRow = sbase + (uint32_t)(wrow + (lane & 15)) * 128;
    const uint32_t bRow = sbase + SB0 + (uint32_t)(wcol + (lane & 15)) * 128;
    const uint32_t vRow = sbase + SVH + (uint32_t)(wcol + (lane & 15)) * 128;
    const uint32_t pRow = sbase + 32768u + (uint32_t)(wrow + (lane & 15)) * 128;

    float num[8][4];
#pragma unroll
    for (int j = 0; j < 8; j++)
#pragma unroll
        for (int v = 0; v < 4; v++) num[j][v] = 0.f;
    float den_[2][2] = {{0.f, 0.f}, {0.f, 0.f}};
    float off_[2][2] = {{0.f, 0.f}, {0.f, 0.f}};

    const float SCALE = 0.25f;
    const float INVH  = 0.08838834764831845f;
    const float SHIFT = 20.0f;

    auto pre_a = [&](int kb, int buf) {
        uint32_t aB = sbase + (uint32_t)(buf * 32768);
#pragma unroll
        for (int qq = 0; qq < 4; qq++) {
            int idx = qq * 256 + t;
            int row = idx >> 3, seg = idx & 7;
            uint32_t d = aB + (((uint32_t)(row * 128 + seg * 16)) ^ ((uint32_t)(row & 7) << 4));
            size_t g = (size_t)(m0 + row) * 512 + kb + seg * 8;
            cp16(d, g_rhi + g);
            cp16(d + SA_LO, g_rlo + g);
        }
    };
    auto pre_b = [&](int j0c, int kb, int buf) {
        uint32_t bB = sbase + SB0 + (uint32_t)(buf * 16384);
#pragma unroll
        for (int qq = 0; qq < 2; qq++) {
            int idx = qq * 256 + t;
            int row = idx >> 3, seg = idx & 7;
            uint32_t d = bB + (((uint32_t)(row * 128 + seg * 16)) ^ ((uint32_t)(row & 7) << 4));
            size_t g = (size_t)(j0c + row) * 512 + kb + seg * 8;
            cp16(d, g_dhi + g);
            cp16(d + SB_LO, g_dlo + g);
        }
    };
    auto pre_v = [&](int jt) {
        const char* srcH = (const char*)g_vth + (size_t)jt * 8192;
        const char* srcL = (const char*)g_vtl + (size_t)jt * 8192;
#pragma unroll
        for (int qq = 0; qq < 2; qq++) {
            int idx = qq * 256 + t;
            cp16(sbase + SVH + (uint32_t)(idx * 16), srcH + idx * 16);
            cp16(sbase + SVH + 8192u + (uint32_t)(idx * 16), srcL + idx * 16);
        }
    };

    pre_a(0, 0);
    pre_b(jt0 * 64, 0, 0);
    pre_v(jt0);
    CP_COMMIT();

#pragma unroll 1
    for (int jt = jt0; jt < jt1; jt++) {
        const int j0 = jt * 64;

        float acc[8][4];
#pragma unroll
        for (int j = 0; j < 8; j++)
#pragma unroll
            for (int v = 0; v < 4; v++) acc[j][v] = 0.f;
        float e[8][4];

#pragma unroll 1
        for (int s = 0; s < 8; s++) {
            CP_WAIT0();
            __syncthreads();

            if (s < 7) {
                int sn = s + 1;
                int kb = (sn < 4) ? sn * 64 : ((sn < 6) ? 384 + (sn - 4) * 64
                                                        : 256 + (sn - 6) * 64);
                pre_a(kb, sn & 1);
                pre_b(j0, kb, sn & 1);
                CP_COMMIT();
            } else if (jt + 1 < jt1) {
                pre_a(0, 0);
                pre_b((jt + 1) * 64, 0, 0);
                CP_COMMIT();
            }

            const uint32_t aHi = aRow + (uint32_t)((s & 1) * 32768);
            const uint32_t bHi = bRow + (uint32_t)((s & 1) * 16384);
#pragma unroll
            for (int ks = 0; ks < 4; ks++) {
                uint32_t ko = ((uint32_t)(ks * 32) + kOff) ^ xm;
                uint32_t ah0[4], ah1[4], al0[4], al1[4];
                ldsm4(ah0[0], ah0[1], ah0[2], ah0[3], aHi + ko);
                ldsm4(ah1[0], ah1[1], ah1[2], ah1[3], aHi + 2048u + ko);
                ldsm4(al0[0], al0[1], al0[2], al0[3], aHi + SA_LO + ko);
                ldsm4(al1[0], al1[1], al1[2], al1[3], aHi + SA_LO + 2048u + ko);
#pragma unroll
                for (int nb = 0; nb < 2; nb++) {
                    uint32_t bh0, bh1, bh2, bh3, bl0, bl1, bl2, bl3;
                    uint32_t ba = bHi + (uint32_t)(nb * 2048) + ko;
                    ldsm4(bh0, bh1, bh2, bh3, ba);
                    ldsm4(bl0, bl1, bl2, bl3, ba + SB_LO);
                    mma16816(acc[nb * 2],     ah0, bh0, bh2);
                    mma16816(acc[nb * 2],     ah0, bl0, bl2);
                    mma16816(acc[nb * 2],     al0, bh0, bh2);
                    mma16816(acc[nb * 2 + 1], ah0, bh1, bh3);
                    mma16816(acc[nb * 2 + 1], ah0, bl1, bl3);
                    mma16816(acc[nb * 2 + 1], al0, bh1, bh3);
                    mma16816(acc[4 + nb * 2],     ah1, bh0, bh2);
                    mma16816(acc[4 + nb * 2],     ah1, bl0, bl2);
                    mma16816(acc[4 + nb * 2],     al1, bh0, bh2);
                    mma16816(acc[4 + nb * 2 + 1], ah1, bh1, bh3);
                    mma16816(acc[4 + nb * 2 + 1], ah1, bl1, bl3);
                    mma16816(acc[4 + nb * 2 + 1], al1, bh1, bh3);
                }
            }

            if (s == 3) {                 // logits -> e, den
#pragma unroll
                for (int j = 0; j < 8; j++) {
                    int m2 = j >> 2;
#pragma unroll
                    for (int v = 0; v < 4; v++) {
                        e[j][v] = __expf(acc[j][v] * SCALE - SHIFT);
                        acc[j][v] = 0.f;
                    }
                    den_[m2][0] += e[j][0] + e[j][1];
                    den_[m2][1] += e[j][2] + e[j][3];
                }
            } else if (s == 5) {          // offset section done
#pragma unroll
                for (int j = 0; j < 8; j++) {
                    int m2 = j >> 2;
                    off_[m2][0] += e[j][0] * tanh_fast(acc[j][0] * INVH)
                                 + e[j][1] * tanh_fast(acc[j][1] * INVH);
                    off_[m2][1] += e[j][2] * tanh_fast(acc[j][2] * INVH)
                                 + e[j][3] * tanh_fast(acc[j][3] * INVH);
#pragma unroll
                    for (int v = 0; v < 4; v++) acc[j][v] = 0.f;
                }
            }
        }

        // ---- P = e * 1.8 * tanh(con) -> chunk-7 A buffer (buf1), hi/lo ----
        __syncthreads();
        {
            char* pPh = dsm + 32768;
            char* pPl = dsm + 49152;
            const int colb = (lane & 3) * 2;
#pragma unroll
            for (int j = 0; j < 8; j++) {
                int m2 = j >> 2;
                int r0 = wrow + m2 * 16 + (lane >> 2);
                int r1 = r0 + 8;
                int c = wcol + (j & 3) * 8 + colb;
                float p0 = e[j][0] * 1.8f * tanh_fast(acc[j][0] * INVH);
                float p1 = e[j][1] * 1.8f * tanh_fast(acc[j][1] * INVH);
                float p2 = e[j][2] * 1.8f * tanh_fast(acc[j][2] * INVH);
                float p3 = e[j][3] * 1.8f * tanh_fast(acc[j][3] * INVH);
                uint32_t h01 = packbf(p0, p1), h23 = packbf(p2, p3);
                uint32_t l01 = packbf(p0 - bf_lo(h01), p1 - bf_hi(h01));
                uint32_t l23 = packbf(p2 - bf_lo(h23), p3 - bf_hi(h23));
                uint32_t d0 = ((uint32_t)(r0 * 128 + c * 2)) ^ ((uint32_t)(r0 & 7) << 4);
                uint32_t d1 = ((uint32_t)(r1 * 128 + c * 2)) ^ ((uint32_t)(r1 & 7) << 4);
                *(uint32_t*)(pPh + d0) = h01;
                *(uint32_t*)(pPl + d0) = l01;
                *(uint32_t*)(pPh + d1) = h23;
                *(uint32_t*)(pPl + d1) = l23;
            }
        }
        __syncthreads();

        // ---- GEMM2: num += P @ V ----
#pragma unroll
        for (int kt = 0; kt < 4; kt++) {
            uint32_t ko = ((uint32_t)(kt * 32) + kOff) ^ xm;
            uint32_t ph0[4], ph1[4], pl0[4], pl1[4];
            ldsm4(ph0[0], ph0[1], ph0[2], ph0[3], pRow + ko);
            ldsm4(ph1[0], ph1[1], ph1[2], ph1[3], pRow + 2048u + ko);
            ldsm4(pl0[0], pl0[1], pl0[2], pl0[3], pRow + SA_LO + ko);
            ldsm4(pl1[0], pl1[1], pl1[2], pl1[3], pRow + SA_LO + 2048u + ko);
#pragma unroll
            for (int nb = 0; nb < 2; nb++) {
                uint32_t vh0, vh1, vh2, vh3, vl0, vl1, vl2, vl3;
                uint32_t va = vRow + (uint32_t)(nb * 2048) + ko;
                ldsm4(vh0, vh1, vh2, vh3, va);
                ldsm4(vl0, vl1, vl2, vl3, va + 8192u);
                mma16816(num[nb * 2],     ph0, vh0, vh2);
                mma16816(num[nb * 2],     ph0, vl0, vl2);
                mma16816(num[nb * 2],     pl0, vh0, vh2);
                mma16816(num[nb * 2 + 1], ph0, vh1, vh3);
                mma16816(num[nb * 2 + 1], ph0, vl1, vl3);
                mma16816(num[nb * 2 + 1], pl0, vh1, vh3);
                mma16816(num[4 + nb * 2],     ph1, vh0, vh2);
                mma16816(num[4 + nb * 2],     ph1, vl0, vl2);
                mma16816(num[4 + nb * 2],     pl1, vh0, vh2);
                mma16816(num[4 + nb * 2 + 1], ph1, vh1, vh3);
                mma16816(num[4 + nb * 2 + 1], ph1, vl1, vl3);
                mma16816(num[4 + nb * 2 + 1], pl1, vh1, vh3);
            }
        }
        __syncthreads();

        if (jt + 1 < jt1) {
            pre_v(jt + 1);
            CP_COMMIT();
        }
    }

    // ---- write num partials ----
    const int colb = (lane & 3) * 2;
    float* np = g_pnum + (size_t)q * NR * 64;
#pragma unroll
    for (int j = 0; j < 8; j++) {
        int m2 = j >> 2;
        int r0 = m0 + wrow + m2 * 16 + (lane >> 2);
        int r1 = r0 + 8;
        int c = wcol + (j & 3) * 8 + colb;
        *(float2*)(np + (size_t)r0 * 64 + c) = make_float2(num[j][0], num[j][1]);
        *(float2*)(np + (size_t)r1 * 64 + c) = make_float2(num[j][2], num[j][3]);
    }

    // ---- den/off: combine the two col-warps via smem, then write ----
    __syncthreads();    // all smem buffers dead now
    float* sden = (float*)dsm;
    float* soff = (float*)(dsm + 1024);
    if (t < 128) { sden[t] = 0.f; soff[t] = 0.f; }
    __syncthreads();
#pragma unroll
    for (int m2 = 0; m2 < 2; m2++)
#pragma unroll
        for (int h = 0; h < 2; h++) {
            float d = den_[m2][h], o = off_[m2][h];
            d += __shfl_xor_sync(0xFFFFFFFFu, d, 1);
            d += __shfl_xor_sync(0xFFFFFFFFu, d, 2);
            o += __shfl_xor_sync(0xFFFFFFFFu, o, 1);
            o += __shfl_xor_sync(0xFFFFFFFFu, o, 2);
            if ((lane & 3) == 0) {
                int r = wrow + m2 * 16 + (lane >> 2) + h * 8;
                atomicAdd(&sden[r], d);
                atomicAdd(&soff[r], o);
            }
        }
    __syncthreads();
    if (t < 128) {
        g_pden[(size_t)q * NR + m0 + t] = sden[t];
        g_poff[(size_t)q * NR + m0 + t] = soff[t];
    }
}

// ---------------------------------------------------------------------------
__global__ __launch_bounds__(256) void epilogue_kernel(float* __restrict__ out)
{
    int idx = blockIdx.x * 256 + threadIdx.x;
    if (idx >= NR * 64) return;
    int row = idx >> 6;
    float num = 0.f, den = 0.f, off = 0.f;
#pragma unroll
    for (int q = 0; q < NQ; q++) {
        num += g_pnum[(size_t)q * NR * 64 + idx];
        den += g_pden[(size_t)q * NR + row];
        off += g_poff[(size_t)q * NR + row];
    }
    out[idx] = (num + off) / den;
}

// ---------------------------------------------------------------------------
extern "C" void kernel_launch(void* const* d_in, const int* in_sizes, int n_in,
                              void* d_out, int out_size)
{
    (void)in_sizes; (void)n_in; (void)out_size;
    const float* pooled = (const float*)d_in[0];
    const float* rlat   = (const float*)d_in[1];
    const float* dlat   = (const float*)d_in[2];
    const float* rpos   = (const float*)d_in[3];
    const float* dpos   = (const float*)d_in[4];
    const float* Wrp = (const float*)d_in[5];   const float* brp = (const float*)d_in[6];
    const float* Wdp = (const float*)d_in[7];   const float* bdp = (const float*)d_in[8];
    const float* Wrc = (const float*)d_in[9];   const float* brc = (const float*)d_in[10];
    const float* Wdc = (const float*)d_in[11];  const float* bdc = (const float*)d_in[12];
    const float* Wro = (const float*)d_in[13];  const float* bro = (const float*)d_in[14];
    const float* Wdo = (const float*)d_in[15];  const float* bdo = (const float*)d_in[16];
    float* out = (float*)d_out;

    cudaFuncSetAttribute(fused_kernel,
                         cudaFuncAttributeMaxDynamicSharedMemorySize, SMEMSZ);
    cudaFuncSetAttribute(proj_mma,
                         cudaFuncAttributeMaxDynamicSharedMemorySize, PJ_SMEM);

    prep_w<<<dim3(512, 2), 128>>>(Wrp, Wrc, Wro, Wdp, Wdc, Wdo);
    prep_in<<<(NR * 128 + 255) / 256, 256>>>(rlat, rpos, NR, 0);
    prep_in<<<(ND * 128 + 255) / 256, 256>>>(dlat, dpos, ND, NR);
    prep_v<<<108, 256>>>(pooled);

    proj_mma<<<dim3(122, 8), 256, PJ_SMEM>>>(brp, bdp, brc, bdc, bro, bdo);

    fused_kernel<<<dim3(108, NQ), 256, SMEMSZ>>>();

    epilogue_kernel<<<(NR * 64 + 255) / 256, 256>>>(out);
}